// round 9
// baseline (speedup 1.0000x reference)
#include <cuda_runtime.h>
#include <cuda_bf16.h>
#include <math.h>
#include <stdint.h>

// ---------------- problem constants ----------------
#define Bq 8
#define Sq 1024
#define Dq 1024
#define DAq 256
#define Hq 16
#define HDq 64
#define Rq 32
#define Mtok (Bq*Sq)   // 8192
#define NCAT (DAq + 3*Dq)   // 3328

// ---------------- scratch (device globals; no allocation) ----------------
__device__ float g_xr  [Mtok*Dq];
__device__ float g_WuT [Dq*Dq];
__device__ float g_WoT [Dq*Dq];
__device__ float g_WkselT[DAq*Dq];
__device__ float g_Wcat[NCAT*Dq];           // [qsel(256) | q | k | v] rows, K=1024
__device__ float g_pooled[Bq*Rq*Dq];
__device__ float g_root  [Bq*Rq*Dq];
__device__ float g_ksel  [Bq*Rq*DAq];
__device__ float g_part[4*256*1024];        // split-K partials (4 MB)
__device__ float g_qsel  [Mtok*DAq];
__device__ unsigned char g_mask[Mtok*Rq];
__device__ float g_q [Mtok*Dq];             // [B,H,S,64]
__device__ float g_k [Mtok*Dq];
__device__ float g_v [Mtok*Dq];
__device__ float g_ctx[Mtok*Dq];

// ---------------- helpers ----------------
__device__ __forceinline__ float rna_tf32(float x) {
    uint32_t r; asm("cvt.rna.tf32.f32 %0, %1;" : "=r"(r) : "f"(x));
    return __uint_as_float(r);
}
__device__ __forceinline__ float warp_max(float v) {
    #pragma unroll
    for (int o = 16; o; o >>= 1) v = fmaxf(v, __shfl_xor_sync(0xffffffffu, v, o));
    return v;
}
__device__ __forceinline__ float warp_sum(float v) {
    #pragma unroll
    for (int o = 16; o; o >>= 1) v += __shfl_xor_sync(0xffffffffu, v, o);
    return v;
}
__device__ __forceinline__ uint32_t smem_u32(const void* p) {
    uint32_t a;
    asm("{ .reg .u64 t; cvta.to.shared.u64 t, %1; cvt.u32.u64 %0, t; }" : "=r"(a) : "l"(p));
    return a;
}

#define CP16(dst, src) \
    asm volatile("cp.async.cg.shared.global [%0], [%1], 16;" :: "r"(dst), "l"(src))
#define CPCOMMIT() asm volatile("cp.async.commit_group;")
#define CPWAIT(n)  asm volatile("cp.async.wait_group %0;" :: "n"(n))

#define LDSM4(r0, r1, r2, r3, addr) \
    asm volatile("ldmatrix.sync.aligned.m8n8.x4.shared.b16 {%0,%1,%2,%3}, [%4];" \
        : "=r"(r0), "=r"(r1), "=r"(r2), "=r"(r3) : "r"(addr))

__device__ __forceinline__ void mma_tf32(float c[4], const uint32_t a[4], const uint32_t b[2]) {
    asm volatile(
        "mma.sync.aligned.m16n8k8.row.col.f32.tf32.tf32.f32 "
        "{%0,%1,%2,%3}, {%4,%5,%6,%7}, {%8,%9}, {%0,%1,%2,%3};"
        : "+f"(c[0]), "+f"(c[1]), "+f"(c[2]), "+f"(c[3])
        : "r"(a[0]), "r"(a[1]), "r"(a[2]), "r"(a[3]), "r"(b[0]), "r"(b[1]));
}

// ---------------- prep kernels ----------------
__global__ void round_copy_kernel(const float4* __restrict__ in, float4* __restrict__ out, int n4) {
    int i = blockIdx.x * blockDim.x + threadIdx.x;
    if (i < n4) {
        float4 v = in[i];
        v.x = rna_tf32(v.x); v.y = rna_tf32(v.y); v.z = rna_tf32(v.z); v.w = rna_tf32(v.w);
        out[i] = v;
    }
}

// All 7 weight transposes in ONE launch.
__global__ void transpose_all_kernel(
    const float* __restrict__ Wq_sel, const float* __restrict__ Wq,
    const float* __restrict__ Wk, const float* __restrict__ Wv,
    const float* __restrict__ Wu, const float* __restrict__ Wo,
    const float* __restrict__ Wk_sel,
    float* __restrict__ Wcat, float* __restrict__ WuT,
    float* __restrict__ WoT, float* __restrict__ WkselT)
{
    __shared__ float t[32][33];
    int tix = blockIdx.x;
    const float* W; float* Wt; int Ndim;
    if (tix < 256)       { W = Wq_sel; Wt = Wcat;                              Ndim = DAq; }
    else if (tix < 1280) { tix -= 256;  W = Wq; Wt = Wcat + (size_t)DAq * Dq;            Ndim = Dq; }
    else if (tix < 2304) { tix -= 1280; W = Wk; Wt = Wcat + (size_t)(DAq + Dq) * Dq;     Ndim = Dq; }
    else if (tix < 3328) { tix -= 2304; W = Wv; Wt = Wcat + (size_t)(DAq + 2 * Dq) * Dq; Ndim = Dq; }
    else if (tix < 4352) { tix -= 3328; W = Wu; Wt = WuT;                                Ndim = Dq; }
    else if (tix < 5376) { tix -= 4352; W = Wo; Wt = WoT;                                Ndim = Dq; }
    else                 { tix -= 5376; W = Wk_sel; Wt = WkselT;                         Ndim = DAq; }
    int ntile = Ndim >> 5;
    int n0 = (tix % ntile) * 32, k0 = (tix / ntile) * 32;
    int tx = threadIdx.x, ty = threadIdx.y;
    #pragma unroll
    for (int i = 0; i < 32; i += 8)
        t[ty + i][tx] = W[(size_t)(k0 + ty + i) * Ndim + n0 + tx];
    __syncthreads();
    #pragma unroll
    for (int i = 0; i < 32; i += 8)
        Wt[(size_t)(n0 + ty + i) * Dq + k0 + tx] = rna_tf32(t[tx][ty + i]);
}

__global__ void pool_kernel(const float* __restrict__ x, float* __restrict__ pooled) {
    int br = blockIdx.x;
    const float* base = x + (size_t)br * 32 * Dq;
    int d4 = threadIdx.x;
    float4 acc = make_float4(0.f, 0.f, 0.f, 0.f);
    #pragma unroll 4
    for (int i = 0; i < 32; i++) {
        float4 v = *(const float4*)(base + (size_t)i * Dq + d4 * 4);
        acc.x += v.x; acc.y += v.y; acc.z += v.z; acc.w += v.w;
    }
    const float s = 1.0f / 32.0f;
    acc.x = rna_tf32(acc.x * s); acc.y = rna_tf32(acc.y * s);
    acc.z = rna_tf32(acc.z * s); acc.w = rna_tf32(acc.w * s);
    *(float4*)(pooled + (size_t)br * Dq + d4 * 4) = acc;
}

// ---------------- big tf32 GEMM: 256x128 CTA tile, 512 thr, 64x32 warp tiles ----------------
// C[M,N] = A[M,K] @ Bt[N,K]^T ; M must be a multiple of 256.
// modes: 0 plain, 2 +resid, 3 store rounded, 4 fused routing (qsel/q/k/v)
#define GBM 256
#define GBN 128
#define GBK 32
#define LDT 36
#define A_FLOATS (GBM * LDT)                 // 9216
#define B_FLOATS (GBN * LDT)                 // 4608
#define STAGE_FLOATS (A_FLOATS + B_FLOATS)   // 13824
#define SM_GEMM_BYTES (2 * STAGE_FLOATS * 4) // 110592

__global__ __launch_bounds__(512, 1)
void mma_gemm(const float* __restrict__ A, const float* __restrict__ Bt,
              float* __restrict__ C, int M, int N, int Kd,
              int mode, const float* __restrict__ resid,
              float* __restrict__ pq, float* __restrict__ pk, float* __restrict__ pv)
{
    extern __shared__ float smf[];
    int tid = threadIdx.x;
    int wid = tid >> 5, lane = tid & 31;
    int warp_row = wid & 3;        // 4 warps along M (64 rows each)
    int warp_col = wid >> 2;       // 4 warps along N (32 cols each)
    int gr = lane >> 2, gc = lane & 3;
    int bm = blockIdx.y * GBM;
    int bn = blockIdx.x * GBN;

    int sel = lane >> 3, l8 = lane & 7;
    int a_row_off = (sel & 1) * 8 + l8;
    int a_col_off = (sel >> 1) * 4;
    int b_row_off = (sel >> 1) * 8 + l8;
    int b_col_off = (sel & 1) * 4;

    float c[4][4][4];
    #pragma unroll
    for (int f = 0; f < 4; f++)
        #pragma unroll
        for (int g = 0; g < 4; g++)
            #pragma unroll
            for (int i = 0; i < 4; i++) c[f][g][i] = 0.f;

    uint32_t sbase = smem_u32(smf);
    const int NK = Kd / GBK;

    // loader: A 2048 cp16 (4/thread) + B 1024 cp16 (2/thread)
    auto load_stage = [&](int p, int k0) {
        uint32_t Abase = sbase + (uint32_t)(p * STAGE_FLOATS) * 4;
        uint32_t Bbase = Abase + (uint32_t)A_FLOATS * 4;
        #pragma unroll
        for (int j = 0; j < 4; j++) {
            int idx = tid + j * 512;          // 0..2047
            int row = idx >> 3, kc = idx & 7;
            CP16(Abase + (uint32_t)(row * LDT + kc * 4) * 4,
                 A + (size_t)(bm + row) * Kd + k0 + kc * 4);
        }
        #pragma unroll
        for (int j = 0; j < 2; j++) {
            int idx = tid + j * 512;          // 0..1023
            int row = idx >> 3, kc = idx & 7;
            CP16(Bbase + (uint32_t)(row * LDT + kc * 4) * 4,
                 Bt + (size_t)(bn + row) * Kd + k0 + kc * 4);
        }
    };

    load_stage(0, 0);
    CPCOMMIT();

    for (int ks = 0; ks < NK; ks++) {
        int p = ks & 1;
        if (ks + 1 < NK) {
            load_stage(p ^ 1, (ks + 1) * GBK);
            CPCOMMIT();
            CPWAIT(1);
        } else {
            CPWAIT(0);
        }
        __syncthreads();

        uint32_t As = sbase + (uint32_t)(p * STAGE_FLOATS) * 4;
        uint32_t Bs = As + (uint32_t)A_FLOATS * 4;
        uint32_t aAddr = As + (uint32_t)((warp_row * 64 + a_row_off) * LDT + a_col_off) * 4;
        uint32_t bAddr = Bs + (uint32_t)((warp_col * 32 + b_row_off) * LDT + b_col_off) * 4;

        #pragma unroll
        for (int kk = 0; kk < 4; kk++) {
            uint32_t a[4][4], b[4][2];
            #pragma unroll
            for (int f = 0; f < 4; f++)
                LDSM4(a[f][0], a[f][1], a[f][2], a[f][3],
                      aAddr + (uint32_t)(f * 16 * LDT + kk * 8) * 4);
            #pragma unroll
            for (int gp = 0; gp < 2; gp++)
                LDSM4(b[2*gp][0], b[2*gp][1], b[2*gp+1][0], b[2*gp+1][1],
                      bAddr + (uint32_t)(gp * 16 * LDT + kk * 8) * 4);
            #pragma unroll
            for (int f = 0; f < 4; f++)
                #pragma unroll
                for (int g = 0; g < 4; g++)
                    mma_tf32(c[f][g], a[f], b[g]);
        }
        __syncthreads();
    }

    // ---- epilogue: two half-tiles of 128 rows through smem ----
    float* stg = smf;   // 128*132*4 = 67584 <= 110592
    #pragma unroll
    for (int half = 0; half < 2; half++) {
        if ((warp_row >> 1) == half) {
            #pragma unroll
            for (int f = 0; f < 4; f++) {
                #pragma unroll
                for (int g = 0; g < 4; g++) {
                    int r0 = (warp_row & 1) * 64 + f * 16 + gr;   // 0..127 within half
                    int c0 = warp_col * 32 + g * 8 + 2 * gc;
                    stg[r0 * 132 + c0]           = c[f][g][0];
                    stg[r0 * 132 + c0 + 1]       = c[f][g][1];
                    stg[(r0 + 8) * 132 + c0]     = c[f][g][2];
                    stg[(r0 + 8) * 132 + c0 + 1] = c[f][g][3];
                }
            }
        }
        __syncthreads();

        int ccol = (tid & 31) * 4;
        #pragma unroll 4
        for (int rr = 0; rr < 8; rr++) {
            int r = (tid >> 5) + rr * 16;      // 0..127
            float4 v;
            v.x = stg[r * 132 + ccol + 0];
            v.y = stg[r * 132 + ccol + 1];
            v.z = stg[r * 132 + ccol + 2];
            v.w = stg[r * 132 + ccol + 3];
            int m = bm + half * 128 + r;
            int n = bn + ccol;
            if (mode == 0) {
                *(float4*)(C + (size_t)m * N + n) = v;
            } else if (mode == 2) {
                float4 rv = *(const float4*)(resid + (size_t)m * N + n);
                v.x += rv.x; v.y += rv.y; v.z += rv.z; v.w += rv.w;
                *(float4*)(C + (size_t)m * N + n) = v;
            } else if (mode == 3) {
                v.x = rna_tf32(v.x); v.y = rna_tf32(v.y);
                v.z = rna_tf32(v.z); v.w = rna_tf32(v.w);
                *(float4*)(C + (size_t)m * N + n) = v;
            } else {
                if (n < DAq) {
                    *(float4*)(C + (size_t)m * DAq + n) = v;
                } else {
                    int n2 = n - DAq;
                    int proj = n2 >> 10, nn = n2 & 1023;
                    int h = nn >> 6, hd = nn & 63;
                    int b = m >> 10, s = m & 1023;
                    float* P = (proj == 0) ? pq : (proj == 1) ? pk : pv;
                    *(float4*)(P + (((size_t)(b * Hq + h)) * Sq + s) * HDq + hd) = v;
                }
            }
        }
        __syncthreads();
    }
}

// ---------------- split-K small GEMM: 64x64 tile, 128 thr, K/4 per z-slice ----------------
#define SKLDT 36
#define SK_STAGE (128 * SKLDT)

__global__ __launch_bounds__(128)
void mma_gemm_sk(const float* __restrict__ A, const float* __restrict__ Bt,
                 float* __restrict__ Cpart, int M, int N, int Kd)
{
    __shared__ float smf[2 * SK_STAGE];
    int tid = threadIdx.x;
    int wid = tid >> 5, lane = tid & 31;
    int warp_row = wid & 1;
    int warp_col = wid >> 1;
    int gr = lane >> 2, gc = lane & 3;
    int bm = blockIdx.y * 64;
    int bn = blockIdx.x * 64;
    int kslice = Kd >> 2;
    int kbase = blockIdx.z * kslice;

    int sel = lane >> 3, l8 = lane & 7;
    int a_row_off = (sel & 1) * 8 + l8;
    int a_col_off = (sel >> 1) * 4;
    int b_row_off = (sel >> 1) * 8 + l8;
    int b_col_off = (sel & 1) * 4;

    float c[2][4][4];
    #pragma unroll
    for (int f = 0; f < 2; f++)
        #pragma unroll
        for (int g = 0; g < 4; g++)
            #pragma unroll
            for (int i = 0; i < 4; i++) c[f][g][i] = 0.f;

    uint32_t sbase = smem_u32(smf);
    const int NK = kslice / GBK;

    auto load_stage = [&](int p, int k0) {
        uint32_t Abase = sbase + (uint32_t)(p * SK_STAGE) * 4;
        uint32_t Bbase = Abase + (uint32_t)(64 * SKLDT) * 4;
        #pragma unroll
        for (int j = 0; j < 4; j++) {
            int idx = tid + j * 128;
            int row = idx >> 3, kc = idx & 7;
            CP16(Abase + (uint32_t)(row * SKLDT + kc * 4) * 4,
                 A + (size_t)(bm + row) * Kd + k0 + kc * 4);
        }
        #pragma unroll
        for (int j = 0; j < 4; j++) {
            int idx = tid + j * 128;
            int row = idx >> 3, kc = idx & 7;
            CP16(Bbase + (uint32_t)(row * SKLDT + kc * 4) * 4,
                 Bt + (size_t)(bn + row) * Kd + k0 + kc * 4);
        }
    };

    load_stage(0, kbase);
    CPCOMMIT();

    for (int ks = 0; ks < NK; ks++) {
        int p = ks & 1;
        if (ks + 1 < NK) {
            load_stage(p ^ 1, kbase + (ks + 1) * GBK);
            CPCOMMIT();
            CPWAIT(1);
        } else {
            CPWAIT(0);
        }
        __syncthreads();

        uint32_t As = sbase + (uint32_t)(p * SK_STAGE) * 4;
        uint32_t Bs = As + (uint32_t)(64 * SKLDT) * 4;
        uint32_t aAddr = As + (uint32_t)((warp_row * 32 + a_row_off) * SKLDT + a_col_off) * 4;
        uint32_t bAddr = Bs + (uint32_t)((warp_col * 32 + b_row_off) * SKLDT + b_col_off) * 4;

        #pragma unroll
        for (int kk = 0; kk < 4; kk++) {
            uint32_t a[2][4], b[4][2];
            #pragma unroll
            for (int f = 0; f < 2; f++)
                LDSM4(a[f][0], a[f][1], a[f][2], a[f][3],
                      aAddr + (uint32_t)(f * 16 * SKLDT + kk * 8) * 4);
            #pragma unroll
            for (int gp = 0; gp < 2; gp++)
                LDSM4(b[2*gp][0], b[2*gp][1], b[2*gp+1][0], b[2*gp+1][1],
                      bAddr + (uint32_t)(gp * 16 * SKLDT + kk * 8) * 4);
            #pragma unroll
            for (int f = 0; f < 2; f++)
                #pragma unroll
                for (int g = 0; g < 4; g++)
                    mma_tf32(c[f][g], a[f], b[g]);
        }
        __syncthreads();
    }

    float* Cp = Cpart + (size_t)blockIdx.z * M * N;
    #pragma unroll
    for (int f = 0; f < 2; f++)
        #pragma unroll
        for (int g = 0; g < 4; g++) {
            int r0 = bm + warp_row * 32 + f * 16 + gr;
            int c0 = bn + warp_col * 32 + g * 8 + 2 * gc;
            *(float2*)(Cp + (size_t)r0 * N + c0)       = make_float2(c[f][g][0], c[f][g][1]);
            *(float2*)(Cp + (size_t)(r0 + 8) * N + c0) = make_float2(c[f][g][2], c[f][g][3]);
        }
}

// reduce 4 split-K partials; optional tf32 rounding
__global__ void reduce4_kernel(const float4* __restrict__ part, float4* __restrict__ dst,
                               int n4, int do_round) {
    int i = blockIdx.x * blockDim.x + threadIdx.x;
    if (i >= n4) return;
    float4 a = part[i], b = part[i + n4], cc = part[i + 2 * n4], d = part[i + 3 * n4];
    float4 v = make_float4(a.x + b.x + cc.x + d.x, a.y + b.y + cc.y + d.y,
                           a.z + b.z + cc.z + d.z, a.w + b.w + cc.w + d.w);
    if (do_round) {
        v.x = rna_tf32(v.x); v.y = rna_tf32(v.y); v.z = rna_tf32(v.z); v.w = rna_tf32(v.w);
    }
    dst[i] = v;
}

// ---------------- block selection ----------------
__global__ __launch_bounds__(256) void select_kernel(
    const float* __restrict__ qsel, const float* __restrict__ ksel,
    unsigned char* __restrict__ mask)
{
    __shared__ float ks[Rq][DAq + 1];
    __shared__ float qrow[8][DAq];
    int b = blockIdx.x;
    int s0 = blockIdx.y * 8;
    int warp = threadIdx.x >> 5, lane = threadIdx.x & 31;
    int s = s0 + warp;

    const float* kp = ksel + (size_t)b * Rq * DAq;
    for (int i = threadIdx.x; i < Rq * DAq; i += 256)
        ks[i >> 8][i & 255] = kp[i];
    const float* qp = qsel + ((size_t)b * Sq + s) * DAq;
    for (int d = lane; d < DAq; d += 32) qrow[warp][d] = qp[d];
    __syncthreads();

    float logit = 0.f;
    #pragma unroll 8
    for (int d = 0; d < DAq; d++)
        logit += qrow[warp][d] * ks[lane][d];
    logit *= 0.0625f;

    float mx = warp_max(logit);
    float e = expf(logit - mx);
    float sum = warp_sum(e);
    float prob = e / sum;
    bool own = (s >> 5) == lane;
    mask[((size_t)b * Sq + s) * Rq + lane] = (prob >= 0.5f || own) ? 1 : 0;
}

// ---------------- block-sparse attention (32 queries per CTA) ----------------
__global__ __launch_bounds__(256) void attn_kernel(
    const float* __restrict__ Q, const float* __restrict__ K,
    const float* __restrict__ V, const unsigned char* __restrict__ mask,
    float* __restrict__ ctx)
{
    __shared__ float qs[32][68];
    __shared__ float kt[32][68];
    __shared__ float vt[32][68];
    __shared__ uint32_t qbits[32];
    __shared__ uint32_t needm_s;

    int bh = blockIdx.x;
    int b = bh >> 4, h = bh & 15;
    int qb = blockIdx.y;
    int s0 = qb * 32;
    int tid = threadIdx.x, warp = tid >> 5, lane = tid & 31;

    const float* Qb = Q + ((size_t)bh * Sq + s0) * HDq;
    #pragma unroll
    for (int i = 0; i < 2; i++) {
        int idx = tid + i * 256;
        int row = idx >> 4, col = (idx & 15) << 2;
        float4 f = *(const float4*)(Qb + row * HDq + col);
        qs[row][col] = f.x; qs[row][col+1] = f.y; qs[row][col+2] = f.z; qs[row][col+3] = f.w;
    }

    if (warp == 0) {
        const unsigned char* mrow = mask + ((size_t)b * Sq + s0 + lane) * Rq;
        uint32_t bits = 0;
        #pragma unroll
        for (int r = 0; r < Rq; r++) bits |= (mrow[r] ? 1u : 0u) << r;
        qbits[lane] = bits;
        #pragma unroll
        for (int o = 16; o; o >>= 1) bits |= __shfl_xor_sync(0xffffffffu, bits, o);
        if (lane == 0) needm_s = bits;
    }
    __syncthreads();
    uint32_t need = needm_s;
    uint32_t myb[4];
    #pragma unroll
    for (int j = 0; j < 4; j++) myb[j] = qbits[warp * 4 + j];

    float mr[4], l[4], c0[4], c1[4];
    #pragma unroll
    for (int j = 0; j < 4; j++) { mr[j] = -INFINITY; l[j] = 0.f; c0[j] = 0.f; c1[j] = 0.f; }

    const float* kbh = K + (size_t)bh * Sq * HDq;
    const float* vbh = V + (size_t)bh * Sq * HDq;

    for (int r = 0; r < 32; r++) {
        if (!((need >> r) & 1u)) continue;
        __syncthreads();
        const float* kb = kbh + (size_t)r * 32 * HDq;
        const float* vb = vbh + (size_t)r * 32 * HDq;
        #pragma unroll
        for (int i = 0; i < 2; i++) {
            int idx = tid + i * 256;
            int row = idx >> 4, col = (idx & 15) << 2;
            float4 f = *(const float4*)(kb + row * HDq + col);
            kt[row][col] = f.x; kt[row][col+1] = f.y; kt[row][col+2] = f.z; kt[row][col+3] = f.w;
            float4 g = *(const float4*)(vb + row * HDq + col);
            vt[row][col] = g.x; vt[row][col+1] = g.y; vt[row][col+2] = g.z; vt[row][col+3] = g.w;
        }
        __syncthreads();

        #pragma unroll
        for (int j = 0; j < 4; j++) {
            if (!((myb[j] >> r) & 1u)) continue;
            int qi = warp * 4 + j;
            float sc = 0.f;
            #pragma unroll
            for (int d = 0; d < HDq; d += 4) {
                float4 kv = *(const float4*)&kt[lane][d];
                float4 qv = *(const float4*)&qs[qi][d];
                sc += kv.x * qv.x + kv.y * qv.y + kv.z * qv.z + kv.w * qv.w;
            }
            sc *= 0.125f;
            float bmax = warp_max(sc);
            float mnew = fmaxf(mr[j], bmax);
            float p = __expf(sc - mnew);
            float scale = __expf(mr[j] - mnew);
            l[j] = l[j] * scale + warp_sum(p);
            c0[j] *= scale; c1[j] *= scale;
            #pragma unroll 8
            for (int t = 0; t < 32; t++) {
                float pj = __shfl_sync(0xffffffffu, p, t);
                c0[j] += pj * vt[t][lane];
                c1[j] += pj * vt[t][lane + 32];
            }
            mr[j] = mnew;
        }
    }

    #pragma unroll
    for (int j = 0; j < 4; j++) {
        int s = s0 + warp * 4 + j;
        float inv = 1.0f / l[j];
        float* cp = ctx + ((size_t)(b * Sq + s)) * Dq + h * HDq;
        cp[lane] = rna_tf32(c0[j] * inv);
        cp[lane + 32] = rna_tf32(c1[j] * inv);
    }
}

// ---------------- host launch ----------------
extern "C" void kernel_launch(void* const* d_in, const int* in_sizes, int n_in,
                              void* d_out, int out_size) {
    const float* x      = (const float*)d_in[0];
    const float* Wu     = (const float*)d_in[1];
    const float* Wk_sel = (const float*)d_in[2];
    const float* Wq_sel = (const float*)d_in[3];
    const float* Wq     = (const float*)d_in[4];
    const float* Wk     = (const float*)d_in[5];
    const float* Wv     = (const float*)d_in[6];
    const float* Wo     = (const float*)d_in[7];
    float* out = (float*)d_out;

    float *xr, *WuT, *WoT, *WkselT, *Wcat, *part;
    float *pooled, *root, *ksel, *qsel, *q, *k, *v, *ctx;
    unsigned char* mask;
    cudaGetSymbolAddress((void**)&xr,     g_xr);
    cudaGetSymbolAddress((void**)&WuT,    g_WuT);
    cudaGetSymbolAddress((void**)&WoT,    g_WoT);
    cudaGetSymbolAddress((void**)&WkselT, g_WkselT);
    cudaGetSymbolAddress((void**)&Wcat,   g_Wcat);
    cudaGetSymbolAddress((void**)&part,   g_part);
    cudaGetSymbolAddress((void**)&pooled, g_pooled);
    cudaGetSymbolAddress((void**)&root,   g_root);
    cudaGetSymbolAddress((void**)&ksel,   g_ksel);
    cudaGetSymbolAddress((void**)&qsel,   g_qsel);
    cudaGetSymbolAddress((void**)&mask,   g_mask);
    cudaGetSymbolAddress((void**)&q,      g_q);
    cudaGetSymbolAddress((void**)&k,      g_k);
    cudaGetSymbolAddress((void**)&v,      g_v);
    cudaGetSymbolAddress((void**)&ctx,    g_ctx);

    cudaFuncSetAttribute(mma_gemm, cudaFuncAttributeMaxDynamicSharedMemorySize, SM_GEMM_BYTES);

    // (1) round x
    round_copy_kernel<<<(Mtok * Dq / 4 + 255) / 256, 256>>>((const float4*)x, (float4*)xr, Mtok * Dq / 4);
    // (2) all weight transposes
    transpose_all_kernel<<<5632, dim3(32, 8)>>>(Wq_sel, Wq, Wk, Wv, Wu, Wo, Wk_sel,
                                                Wcat, WuT, WoT, WkselT);
    // (3) pooling
    pool_kernel<<<Bq * Rq, 256>>>(x, pooled);
    // (4-5) root = pooled @ Wu (split-K 4 + rounded reduce)
    mma_gemm_sk<<<dim3(Dq / 64, (Bq * Rq) / 64, 4), 128>>>(pooled, WuT, part, Bq * Rq, Dq, Dq);
    reduce4_kernel<<<(Bq * Rq * Dq / 4 + 255) / 256, 256>>>((const float4*)part, (float4*)root,
                                                            Bq * Rq * Dq / 4, 1);
    // (6-7) ksel = root @ Wk_sel (split-K 4 + plain reduce)
    mma_gemm_sk<<<dim3(DAq / 64, (Bq * Rq) / 64, 4), 128>>>(root, WkselT, part, Bq * Rq, DAq, Dq);
    reduce4_kernel<<<(Bq * Rq * DAq / 4 + 255) / 256, 256>>>((const float4*)part, (float4*)ksel,
                                                             Bq * Rq * DAq / 4, 0);
    // (8) fused: [qsel | q | k | v] = xr @ Wcat^T     (256-row tiles)
    mma_gemm<<<dim3(NCAT / GBN, Mtok / GBM), 512, SM_GEMM_BYTES>>>(
        xr, Wcat, qsel, Mtok, NCAT, Dq, 4, nullptr, q, k, v);
    // (9) selection mask
    select_kernel<<<dim3(Bq, Sq / 8), 256>>>(qsel, ksel, mask);
    // (10) attention
    attn_kernel<<<dim3(Bq * Hq, Sq / 32), 256>>>(q, k, v, mask, ctx);
    // (11) out = ctx @ Wo + x
    mma_gemm<<<dim3(Dq / GBN, Mtok / GBM), 512, SM_GEMM_BYTES>>>(
        ctx, WoT, out, Mtok, Dq, Dq, 2, x, nullptr, nullptr, nullptr);
}

// round 11
// speedup vs baseline: 1.5559x; 1.5559x over previous
#include <cuda_runtime.h>
#include <cuda_fp16.h>
#include <math.h>
#include <stdint.h>

// ---------------- problem constants ----------------
#define Bq 8
#define Sq 1024
#define Dq 1024
#define DAq 256
#define Hq 16
#define HDq 64
#define Rq 32
#define Mtok (Bq*Sq)   // 8192

// ---------------- scratch (device globals; no allocation) ----------------
__device__ float g_xr  [Mtok*Dq];                 // tf32-rounded x (for qsel GEMM)
__device__ __half g_xh[Mtok*Dq];                  // fp16 x (for qkv GEMM)
__device__ float g_WuT [Dq*Dq];
__device__ float g_WqselT[DAq*Dq];
__device__ float g_WkselT[DAq*Dq];
__device__ __half g_Wqkv_h[3*Dq*Dq];              // [q|k|v] transposed fp16
__device__ __half g_WoT_h[Dq*Dq];
__device__ float g_pooled[Bq*Rq*Dq];
__device__ float g_root  [Bq*Rq*Dq];
__device__ float g_ksel  [Bq*Rq*DAq];
__device__ float g_part[4*256*1024];
__device__ float g_qsel  [Mtok*DAq];
__device__ unsigned char g_mask[Mtok*Rq];
__device__ float g_q [Mtok*Dq];                   // [B,H,S,64]
__device__ float g_k [Mtok*Dq];
__device__ float g_v [Mtok*Dq];
__device__ __half g_ctx_h[Mtok*Dq];               // [B,S,D] fp16

// ---------------- helpers ----------------
__device__ __forceinline__ float rna_tf32(float x) {
    uint32_t r; asm("cvt.rna.tf32.f32 %0, %1;" : "=r"(r) : "f"(x));
    return __uint_as_float(r);
}
__device__ __forceinline__ float warp_max(float v) {
    #pragma unroll
    for (int o = 16; o; o >>= 1) v = fmaxf(v, __shfl_xor_sync(0xffffffffu, v, o));
    return v;
}
__device__ __forceinline__ float warp_sum(float v) {
    #pragma unroll
    for (int o = 16; o; o >>= 1) v += __shfl_xor_sync(0xffffffffu, v, o);
    return v;
}
__device__ __forceinline__ uint32_t smem_u32(const void* p) {
    uint32_t a;
    asm("{ .reg .u64 t; cvta.to.shared.u64 t, %1; cvt.u32.u64 %0, t; }" : "=r"(a) : "l"(p));
    return a;
}

#define CP16(dst, src) \
    asm volatile("cp.async.cg.shared.global [%0], [%1], 16;" :: "r"(dst), "l"(src))
#define CPCOMMIT() asm volatile("cp.async.commit_group;")
#define CPWAIT(n)  asm volatile("cp.async.wait_group %0;" :: "n"(n))

#define LDSM4(r0, r1, r2, r3, addr) \
    asm volatile("ldmatrix.sync.aligned.m8n8.x4.shared.b16 {%0,%1,%2,%3}, [%4];" \
        : "=r"(r0), "=r"(r1), "=r"(r2), "=r"(r3) : "r"(addr))

__device__ __forceinline__ void mma_tf32(float c[4], const uint32_t a[4], const uint32_t b[2]) {
    asm volatile(
        "mma.sync.aligned.m16n8k8.row.col.f32.tf32.tf32.f32 "
        "{%0,%1,%2,%3}, {%4,%5,%6,%7}, {%8,%9}, {%0,%1,%2,%3};"
        : "+f"(c[0]), "+f"(c[1]), "+f"(c[2]), "+f"(c[3])
        : "r"(a[0]), "r"(a[1]), "r"(a[2]), "r"(a[3]), "r"(b[0]), "r"(b[1]));
}
__device__ __forceinline__ void mma_f16(float c[4], const uint32_t a[4], const uint32_t b[2]) {
    asm volatile(
        "mma.sync.aligned.m16n8k16.row.col.f32.f16.f16.f32 "
        "{%0,%1,%2,%3}, {%4,%5,%6,%7}, {%8,%9}, {%0,%1,%2,%3};"
        : "+f"(c[0]), "+f"(c[1]), "+f"(c[2]), "+f"(c[3])
        : "r"(a[0]), "r"(a[1]), "r"(a[2]), "r"(a[3]), "r"(b[0]), "r"(b[1]));
}

// ---------------- prep kernels ----------------
// x -> xr (tf32-rounded fp32) and xh (fp16)
__global__ void round_copy_kernel(const float4* __restrict__ in, float4* __restrict__ xr,
                                  __half2* __restrict__ xh, int n4) {
    int i = blockIdx.x * blockDim.x + threadIdx.x;
    if (i < n4) {
        float4 v = in[i];
        float4 r;
        r.x = rna_tf32(v.x); r.y = rna_tf32(v.y); r.z = rna_tf32(v.z); r.w = rna_tf32(v.w);
        xr[i] = r;
        xh[2 * i]     = __floats2half2_rn(v.x, v.y);
        xh[2 * i + 1] = __floats2half2_rn(v.z, v.w);
    }
}

// All 7 weight transposes in ONE launch; qkv+Wo -> fp16, rest -> tf32-fp32.
__global__ void transpose_all_kernel(
    const float* __restrict__ Wq_sel, const float* __restrict__ Wq,
    const float* __restrict__ Wk, const float* __restrict__ Wv,
    const float* __restrict__ Wu, const float* __restrict__ Wo,
    const float* __restrict__ Wk_sel,
    float* __restrict__ WqselT, __half* __restrict__ Wqkv_h,
    float* __restrict__ WuT, __half* __restrict__ WoT_h,
    float* __restrict__ WkselT)
{
    __shared__ float t[32][33];
    int tix = blockIdx.x;
    const float* W; int Ndim, seg;
    if (tix < 256)       { seg = 0; W = Wq_sel; Ndim = DAq; }
    else if (tix < 1280) { seg = 1; tix -= 256;  W = Wq; Ndim = Dq; }
    else if (tix < 2304) { seg = 2; tix -= 1280; W = Wk; Ndim = Dq; }
    else if (tix < 3328) { seg = 3; tix -= 2304; W = Wv; Ndim = Dq; }
    else if (tix < 4352) { seg = 4; tix -= 3328; W = Wu; Ndim = Dq; }
    else if (tix < 5376) { seg = 5; tix -= 4352; W = Wo; Ndim = Dq; }
    else                 { seg = 6; tix -= 5376; W = Wk_sel; Ndim = DAq; }
    int ntile = Ndim >> 5;
    int n0 = (tix % ntile) * 32, k0 = (tix / ntile) * 32;
    int tx = threadIdx.x, ty = threadIdx.y;
    #pragma unroll
    for (int i = 0; i < 32; i += 8)
        t[ty + i][tx] = W[(size_t)(k0 + ty + i) * Ndim + n0 + tx];
    __syncthreads();
    if (seg >= 1 && seg <= 3) {
        __half* dst = Wqkv_h + (size_t)(seg - 1) * Dq * Dq;
        #pragma unroll
        for (int i = 0; i < 32; i += 8)
            dst[(size_t)(n0 + ty + i) * Dq + k0 + tx] = __float2half_rn(t[tx][ty + i]);
    } else if (seg == 5) {
        #pragma unroll
        for (int i = 0; i < 32; i += 8)
            WoT_h[(size_t)(n0 + ty + i) * Dq + k0 + tx] = __float2half_rn(t[tx][ty + i]);
    } else {
        float* dst = (seg == 0) ? WqselT : (seg == 4) ? WuT : WkselT;
        #pragma unroll
        for (int i = 0; i < 32; i += 8)
            dst[(size_t)(n0 + ty + i) * Dq + k0 + tx] = rna_tf32(t[tx][ty + i]);
    }
}

__global__ void pool_kernel(const float* __restrict__ x, float* __restrict__ pooled) {
    int br = blockIdx.x;
    const float* base = x + (size_t)br * 32 * Dq;
    int d4 = threadIdx.x;
    float4 acc = make_float4(0.f, 0.f, 0.f, 0.f);
    #pragma unroll 4
    for (int i = 0; i < 32; i++) {
        float4 v = *(const float4*)(base + (size_t)i * Dq + d4 * 4);
        acc.x += v.x; acc.y += v.y; acc.z += v.z; acc.w += v.w;
    }
    const float s = 1.0f / 32.0f;
    acc.x = rna_tf32(acc.x * s); acc.y = rna_tf32(acc.y * s);
    acc.z = rna_tf32(acc.z * s); acc.w = rna_tf32(acc.w * s);
    *(float4*)(pooled + (size_t)br * Dq + d4 * 4) = acc;
}

// ---------------- tf32 mma.sync GEMM (R8-proven: 128x128, 256 thr) ----------------
#define GBM 128
#define GBN 128
#define GBK 32
#define LDT 36
#define STG_FLOATS (GBM * LDT)       // 4608
#define SM_GEMM_BYTES (4 * STG_FLOATS * 4)   // 73728

__global__ __launch_bounds__(256, 2)
void mma_gemm(const float* __restrict__ A, const float* __restrict__ Bt,
              float* __restrict__ C, int M, int N, int Kd)
{
    extern __shared__ float smf[];
    int tid = threadIdx.x;
    int wid = tid >> 5, lane = tid & 31;
    int warp_row = wid & 1;
    int warp_col = wid >> 1;
    int gr = lane >> 2, gc = lane & 3;
    int bm = blockIdx.y * GBM;
    int bn = blockIdx.x * GBN;

    int sel = lane >> 3, l8 = lane & 7;
    int a_row_off = (sel & 1) * 8 + l8;
    int a_col_off = (sel >> 1) * 4;
    int b_row_off = (sel >> 1) * 8 + l8;
    int b_col_off = (sel & 1) * 4;

    float c[4][4][4];
    #pragma unroll
    for (int f = 0; f < 4; f++)
        #pragma unroll
        for (int g = 0; g < 4; g++)
            #pragma unroll
            for (int i = 0; i < 4; i++) c[f][g][i] = 0.f;

    uint32_t sbase = smem_u32(smf);
    const int NK = Kd / GBK;

    auto load_stage = [&](int p, int k0) {
        uint32_t Abase = sbase + (uint32_t)(p * 2 * STG_FLOATS) * 4;
        uint32_t Bbase = Abase + STG_FLOATS * 4;
        #pragma unroll
        for (int j = 0; j < 4; j++) {
            int idx = tid + j * 256;
            int row = idx >> 3, kc = idx & 7;
            CP16(Abase + (uint32_t)(row * LDT + kc * 4) * 4,
                 A + (size_t)(bm + row) * Kd + k0 + kc * 4);
        }
        #pragma unroll
        for (int j = 0; j < 4; j++) {
            int idx = tid + j * 256;
            int row = idx >> 3, kc = idx & 7;
            CP16(Bbase + (uint32_t)(row * LDT + kc * 4) * 4,
                 Bt + (size_t)(bn + row) * Kd + k0 + kc * 4);
        }
    };

    load_stage(0, 0);
    CPCOMMIT();

    for (int ks = 0; ks < NK; ks++) {
        int p = ks & 1;
        if (ks + 1 < NK) {
            load_stage(p ^ 1, (ks + 1) * GBK);
            CPCOMMIT();
            CPWAIT(1);
        } else {
            CPWAIT(0);
        }
        __syncthreads();

        uint32_t As = sbase + (uint32_t)(p * 2 * STG_FLOATS) * 4;
        uint32_t Bs = As + STG_FLOATS * 4;
        uint32_t aAddr = As + (uint32_t)((warp_row * 64 + a_row_off) * LDT + a_col_off) * 4;
        uint32_t bAddr = Bs + (uint32_t)((warp_col * 32 + b_row_off) * LDT + b_col_off) * 4;

        #pragma unroll
        for (int kk = 0; kk < 4; kk++) {
            uint32_t a[4][4], b[4][2];
            #pragma unroll
            for (int f = 0; f < 4; f++)
                LDSM4(a[f][0], a[f][1], a[f][2], a[f][3],
                      aAddr + (uint32_t)(f * 16 * LDT + kk * 8) * 4);
            #pragma unroll
            for (int gp = 0; gp < 2; gp++)
                LDSM4(b[2*gp][0], b[2*gp][1], b[2*gp+1][0], b[2*gp+1][1],
                      bAddr + (uint32_t)(gp * 16 * LDT + kk * 8) * 4);
            #pragma unroll
            for (int f = 0; f < 4; f++)
                #pragma unroll
                for (int g = 0; g < 4; g++)
                    mma_tf32(c[f][g], a[f], b[g]);
        }
        __syncthreads();
    }

    float* stg = smf;
    #pragma unroll
    for (int f = 0; f < 4; f++)
        #pragma unroll
        for (int g = 0; g < 4; g++) {
            int r0 = warp_row * 64 + f * 16 + gr;
            int c0 = warp_col * 32 + g * 8 + 2 * gc;
            stg[r0 * 132 + c0]           = c[f][g][0];
            stg[r0 * 132 + c0 + 1]       = c[f][g][1];
            stg[(r0 + 8) * 132 + c0]     = c[f][g][2];
            stg[(r0 + 8) * 132 + c0 + 1] = c[f][g][3];
        }
    __syncthreads();

    int ccol = (tid & 31) * 4;
    #pragma unroll 4
    for (int rr = 0; rr < 16; rr++) {
        int r = (tid >> 5) + rr * 8;
        float4 v;
        v.x = stg[r * 132 + ccol + 0];
        v.y = stg[r * 132 + ccol + 1];
        v.z = stg[r * 132 + ccol + 2];
        v.w = stg[r * 132 + ccol + 3];
        *(float4*)(C + (size_t)(bm + r) * N + bn + ccol) = v;
    }
}

// ---------------- fp16 mma.sync GEMM: 128x128, 256 thr, GBK=64 ----------------
// modes: 2 = +resid (fp32), 4 = qkv routing to [B,H,S,64]
#define GBKB 64
#define ROWB 144                      // bytes per row: 64 fp16 (128B) + 16B pad
#define OP_H_BYTES (128 * ROWB)       // 18432
#define STAGE_H_BYTES (2 * OP_H_BYTES)    // 36864; x2 stages = 73728 = SM_GEMM_BYTES

__global__ __launch_bounds__(256, 2)
void mma_gemm_h(const __half* __restrict__ A, const __half* __restrict__ Bt,
                float* __restrict__ C, int M, int N, int Kd,
                int mode, const float* __restrict__ resid,
                float* __restrict__ pq, float* __restrict__ pk, float* __restrict__ pv)
{
    extern __shared__ float smf[];
    int tid = threadIdx.x;
    int wid = tid >> 5, lane = tid & 31;
    int warp_row = wid & 1;        // 64 rows each
    int warp_col = wid >> 1;       // 32 cols each
    int gr = lane >> 2, gc = lane & 3;
    int bm = blockIdx.y * GBM;
    int bn = blockIdx.x * GBN;

    int sel = lane >> 3, l8 = lane & 7;
    int a_row_off = (sel & 1) * 8 + l8;
    int a_col16 = (sel >> 1) * 16;     // bytes
    int b_row_off = (sel >> 1) * 8 + l8;
    int b_col16 = (sel & 1) * 16;      // bytes

    float c[4][4][4];
    #pragma unroll
    for (int f = 0; f < 4; f++)
        #pragma unroll
        for (int g = 0; g < 4; g++)
            #pragma unroll
            for (int i = 0; i < 4; i++) c[f][g][i] = 0.f;

    uint32_t sbase = smem_u32(smf);
    const int NK = Kd / GBKB;          // 16

    auto load_stage = [&](int p, int k0) {
        uint32_t Abase = sbase + (uint32_t)(p * STAGE_H_BYTES);
        uint32_t Bbase = Abase + OP_H_BYTES;
        #pragma unroll
        for (int j = 0; j < 4; j++) {
            int idx = tid + j * 256;
            int row = idx >> 3, kc = idx & 7;
            CP16(Abase + (uint32_t)(row * ROWB + kc * 16),
                 A + (size_t)(bm + row) * Kd + k0 + kc * 8);
        }
        #pragma unroll
        for (int j = 0; j < 4; j++) {
            int idx = tid + j * 256;
            int row = idx >> 3, kc = idx & 7;
            CP16(Bbase + (uint32_t)(row * ROWB + kc * 16),
                 Bt + (size_t)(bn + row) * Kd + k0 + kc * 8);
        }
    };

    load_stage(0, 0);
    CPCOMMIT();

    for (int ks = 0; ks < NK; ks++) {
        int p = ks & 1;
        if (ks + 1 < NK) {
            load_stage(p ^ 1, (ks + 1) * GBKB);
            CPCOMMIT();
            CPWAIT(1);
        } else {
            CPWAIT(0);
        }
        __syncthreads();

        uint32_t As = sbase + (uint32_t)(p * STAGE_H_BYTES);
        uint32_t Bs = As + OP_H_BYTES;
        uint32_t aAddr = As + (uint32_t)((warp_row * 64 + a_row_off) * ROWB + a_col16);
        uint32_t bAddr = Bs + (uint32_t)((warp_col * 32 + b_row_off) * ROWB + b_col16);

        #pragma unroll
        for (int kk = 0; kk < 4; kk++) {     // 4 k16 steps per 64-chunk
            uint32_t a[4][4], b[4][2];
            #pragma unroll
            for (int f = 0; f < 4; f++)
                LDSM4(a[f][0], a[f][1], a[f][2], a[f][3],
                      aAddr + (uint32_t)(f * 16 * ROWB + kk * 32));
            #pragma unroll
            for (int gp = 0; gp < 2; gp++)
                LDSM4(b[2*gp][0], b[2*gp][1], b[2*gp+1][0], b[2*gp+1][1],
                      bAddr + (uint32_t)(gp * 16 * ROWB + kk * 32));
            #pragma unroll
            for (int f = 0; f < 4; f++)
                #pragma unroll
                for (int g = 0; g < 4; g++)
                    mma_f16(c[f][g], a[f], b[g]);
        }
        __syncthreads();
    }

    float* stg = smf;
    #pragma unroll
    for (int f = 0; f < 4; f++)
        #pragma unroll
        for (int g = 0; g < 4; g++) {
            int r0 = warp_row * 64 + f * 16 + gr;
            int c0 = warp_col * 32 + g * 8 + 2 * gc;
            stg[r0 * 132 + c0]           = c[f][g][0];
            stg[r0 * 132 + c0 + 1]       = c[f][g][1];
            stg[(r0 + 8) * 132 + c0]     = c[f][g][2];
            stg[(r0 + 8) * 132 + c0 + 1] = c[f][g][3];
        }
    __syncthreads();

    int ccol = (tid & 31) * 4;
    #pragma unroll 4
    for (int rr = 0; rr < 16; rr++) {
        int r = (tid >> 5) + rr * 8;
        float4 v;
        v.x = stg[r * 132 + ccol + 0];
        v.y = stg[r * 132 + ccol + 1];
        v.z = stg[r * 132 + ccol + 2];
        v.w = stg[r * 132 + ccol + 3];
        int m = bm + r;
        int n = bn + ccol;
        if (mode == 2) {
            float4 rv = *(const float4*)(resid + (size_t)m * N + n);
            v.x += rv.x; v.y += rv.y; v.z += rv.z; v.w += rv.w;
            *(float4*)(C + (size_t)m * N + n) = v;
        } else {
            int proj = n >> 10, nn = n & 1023;
            int h = nn >> 6, hd = nn & 63;
            int b = m >> 10, s = m & 1023;
            float* P = (proj == 0) ? pq : (proj == 1) ? pk : pv;
            *(float4*)(P + (((size_t)(b * Hq + h)) * Sq + s) * HDq + hd) = v;
        }
    }
}

// ---------------- split-K small GEMM (tf32, unchanged from R8) ----------------
#define SKLDT 36
#define SK_STAGE (128 * SKLDT)

__global__ __launch_bounds__(128)
void mma_gemm_sk(const float* __restrict__ A, const float* __restrict__ Bt,
                 float* __restrict__ Cpart, int M, int N, int Kd)
{
    __shared__ float smf[2 * SK_STAGE];
    int tid = threadIdx.x;
    int wid = tid >> 5, lane = tid & 31;
    int warp_row = wid & 1;
    int warp_col = wid >> 1;
    int gr = lane >> 2, gc = lane & 3;
    int bm = blockIdx.y * 64;
    int bn = blockIdx.x * 64;
    int kslice = Kd >> 2;
    int kbase = blockIdx.z * kslice;

    int sel = lane >> 3, l8 = lane & 7;
    int a_row_off = (sel & 1) * 8 + l8;
    int a_col_off = (sel >> 1) * 4;
    int b_row_off = (sel >> 1) * 8 + l8;
    int b_col_off = (sel & 1) * 4;

    float c[2][4][4];
    #pragma unroll
    for (int f = 0; f < 2; f++)
        #pragma unroll
        for (int g = 0; g < 4; g++)
            #pragma unroll
            for (int i = 0; i < 4; i++) c[f][g][i] = 0.f;

    uint32_t sbase = smem_u32(smf);
    const int NK = kslice / GBK;

    auto load_stage = [&](int p, int k0) {
        uint32_t Abase = sbase + (uint32_t)(p * SK_STAGE) * 4;
        uint32_t Bbase = Abase + (uint32_t)(64 * SKLDT) * 4;
        #pragma unroll
        for (int j = 0; j < 4; j++) {
            int idx = tid + j * 128;
            int row = idx >> 3, kc = idx & 7;
            CP16(Abase + (uint32_t)(row * SKLDT + kc * 4) * 4,
                 A + (size_t)(bm + row) * Kd + k0 + kc * 4);
        }
        #pragma unroll
        for (int j = 0; j < 4; j++) {
            int idx = tid + j * 128;
            int row = idx >> 3, kc = idx & 7;
            CP16(Bbase + (uint32_t)(row * SKLDT + kc * 4) * 4,
                 Bt + (size_t)(bn + row) * Kd + k0 + kc * 4);
        }
    };

    load_stage(0, kbase);
    CPCOMMIT();

    for (int ks = 0; ks < NK; ks++) {
        int p = ks & 1;
        if (ks + 1 < NK) {
            load_stage(p ^ 1, kbase + (ks + 1) * GBK);
            CPCOMMIT();
            CPWAIT(1);
        } else {
            CPWAIT(0);
        }
        __syncthreads();

        uint32_t As = sbase + (uint32_t)(p * SK_STAGE) * 4;
        uint32_t Bs = As + (uint32_t)(64 * SKLDT) * 4;
        uint32_t aAddr = As + (uint32_t)((warp_row * 32 + a_row_off) * SKLDT + a_col_off) * 4;
        uint32_t bAddr = Bs + (uint32_t)((warp_col * 32 + b_row_off) * SKLDT + b_col_off) * 4;

        #pragma unroll
        for (int kk = 0; kk < 4; kk++) {
            uint32_t a[2][4], b[4][2];
            #pragma unroll
            for (int f = 0; f < 2; f++)
                LDSM4(a[f][0], a[f][1], a[f][2], a[f][3],
                      aAddr + (uint32_t)(f * 16 * SKLDT + kk * 8) * 4);
            #pragma unroll
            for (int gp = 0; gp < 2; gp++)
                LDSM4(b[2*gp][0], b[2*gp][1], b[2*gp+1][0], b[2*gp+1][1],
                      bAddr + (uint32_t)(gp * 16 * SKLDT + kk * 8) * 4);
            #pragma unroll
            for (int f = 0; f < 2; f++)
                #pragma unroll
                for (int g = 0; g < 4; g++)
                    mma_tf32(c[f][g], a[f], b[g]);
        }
        __syncthreads();
    }

    float* Cp = Cpart + (size_t)blockIdx.z * M * N;
    #pragma unroll
    for (int f = 0; f < 2; f++)
        #pragma unroll
        for (int g = 0; g < 4; g++) {
            int r0 = bm + warp_row * 32 + f * 16 + gr;
            int c0 = bn + warp_col * 32 + g * 8 + 2 * gc;
            *(float2*)(Cp + (size_t)r0 * N + c0)       = make_float2(c[f][g][0], c[f][g][1]);
            *(float2*)(Cp + (size_t)(r0 + 8) * N + c0) = make_float2(c[f][g][2], c[f][g][3]);
        }
}

__global__ void reduce4_kernel(const float4* __restrict__ part, float4* __restrict__ dst,
                               int n4, int do_round) {
    int i = blockIdx.x * blockDim.x + threadIdx.x;
    if (i >= n4) return;
    float4 a = part[i], b = part[i + n4], cc = part[i + 2 * n4], d = part[i + 3 * n4];
    float4 v = make_float4(a.x + b.x + cc.x + d.x, a.y + b.y + cc.y + d.y,
                           a.z + b.z + cc.z + d.z, a.w + b.w + cc.w + d.w);
    if (do_round) {
        v.x = rna_tf32(v.x); v.y = rna_tf32(v.y); v.z = rna_tf32(v.z); v.w = rna_tf32(v.w);
    }
    dst[i] = v;
}

// ---------------- block selection ----------------
__global__ __launch_bounds__(256) void select_kernel(
    const float* __restrict__ qsel, const float* __restrict__ ksel,
    unsigned char* __restrict__ mask)
{
    __shared__ float ks[Rq][DAq + 1];
    __shared__ float qrow[8][DAq];
    int b = blockIdx.x;
    int s0 = blockIdx.y * 8;
    int warp = threadIdx.x >> 5, lane = threadIdx.x & 31;
    int s = s0 + warp;

    const float* kp = ksel + (size_t)b * Rq * DAq;
    for (int i = threadIdx.x; i < Rq * DAq; i += 256)
        ks[i >> 8][i & 255] = kp[i];
    const float* qp = qsel + ((size_t)b * Sq + s) * DAq;
    for (int d = lane; d < DAq; d += 32) qrow[warp][d] = qp[d];
    __syncthreads();

    float logit = 0.f;
    #pragma unroll 8
    for (int d = 0; d < DAq; d++)
        logit += qrow[warp][d] * ks[lane][d];
    logit *= 0.0625f;

    float mx = warp_max(logit);
    float e = expf(logit - mx);
    float sum = warp_sum(e);
    float prob = e / sum;
    bool own = (s >> 5) == lane;
    mask[((size_t)b * Sq + s) * Rq + lane] = (prob >= 0.5f || own) ? 1 : 0;
}

// ---------------- block-sparse attention (32 queries per CTA) ----------------
__global__ __launch_bounds__(256) void attn_kernel(
    const float* __restrict__ Q, const float* __restrict__ K,
    const float* __restrict__ V, const unsigned char* __restrict__ mask,
    __half* __restrict__ ctx)
{
    __shared__ float qs[32][68];
    __shared__ float kt[32][68];
    __shared__ float vt[32][68];
    __shared__ uint32_t qbits[32];
    __shared__ uint32_t needm_s;

    int bh = blockIdx.x;
    int b = bh >> 4, h = bh & 15;
    int qb = blockIdx.y;
    int s0 = qb * 32;
    int tid = threadIdx.x, warp = tid >> 5, lane = tid & 31;

    const float* Qb = Q + ((size_t)bh * Sq + s0) * HDq;
    #pragma unroll
    for (int i = 0; i < 2; i++) {
        int idx = tid + i * 256;
        int row = idx >> 4, col = (idx & 15) << 2;
        float4 f = *(const float4*)(Qb + row * HDq + col);
        qs[row][col] = f.x; qs[row][col+1] = f.y; qs[row][col+2] = f.z; qs[row][col+3] = f.w;
    }

    if (warp == 0) {
        const unsigned char* mrow = mask + ((size_t)b * Sq + s0 + lane) * Rq;
        uint32_t bits = 0;
        #pragma unroll
        for (int r = 0; r < Rq; r++) bits |= (mrow[r] ? 1u : 0u) << r;
        qbits[lane] = bits;
        #pragma unroll
        for (int o = 16; o; o >>= 1) bits |= __shfl_xor_sync(0xffffffffu, bits, o);
        if (lane == 0) needm_s = bits;
    }
    __syncthreads();
    uint32_t need = needm_s;
    uint32_t myb[4];
    #pragma unroll
    for (int j = 0; j < 4; j++) myb[j] = qbits[warp * 4 + j];

    float mr[4], l[4], c0[4], c1[4];
    #pragma unroll
    for (int j = 0; j < 4; j++) { mr[j] = -INFINITY; l[j] = 0.f; c0[j] = 0.f; c1[j] = 0.f; }

    const float* kbh = K + (size_t)bh * Sq * HDq;
    const float* vbh = V + (size_t)bh * Sq * HDq;

    for (int r = 0; r < 32; r++) {
        if (!((need >> r) & 1u)) continue;
        __syncthreads();
        const float* kb = kbh + (size_t)r * 32 * HDq;
        const float* vb = vbh + (size_t)r * 32 * HDq;
        #pragma unroll
        for (int i = 0; i < 2; i++) {
            int idx = tid + i * 256;
            int row = idx >> 4, col = (idx & 15) << 2;
            float4 f = *(const float4*)(kb + row * HDq + col);
            kt[row][col] = f.x; kt[row][col+1] = f.y; kt[row][col+2] = f.z; kt[row][col+3] = f.w;
            float4 g = *(const float4*)(vb + row * HDq + col);
            vt[row][col] = g.x; vt[row][col+1] = g.y; vt[row][col+2] = g.z; vt[row][col+3] = g.w;
        }
        __syncthreads();

        #pragma unroll
        for (int j = 0; j < 4; j++) {
            if (!((myb[j] >> r) & 1u)) continue;
            int qi = warp * 4 + j;
            float sc = 0.f;
            #pragma unroll
            for (int d = 0; d < HDq; d += 4) {
                float4 kv = *(const float4*)&kt[lane][d];
                float4 qv = *(const float4*)&qs[qi][d];
                sc += kv.x * qv.x + kv.y * qv.y + kv.z * qv.z + kv.w * qv.w;
            }
            sc *= 0.125f;
            float bmax = warp_max(sc);
            float mnew = fmaxf(mr[j], bmax);
            float p = __expf(sc - mnew);
            float scale = __expf(mr[j] - mnew);
            l[j] = l[j] * scale + warp_sum(p);
            c0[j] *= scale; c1[j] *= scale;
            #pragma unroll 8
            for (int t = 0; t < 32; t++) {
                float pj = __shfl_sync(0xffffffffu, p, t);
                c0[j] += pj * vt[t][lane];
                c1[j] += pj * vt[t][lane + 32];
            }
            mr[j] = mnew;
        }
    }

    #pragma unroll
    for (int j = 0; j < 4; j++) {
        int s = s0 + warp * 4 + j;
        float inv = 1.0f / l[j];
        __half* cp = ctx + ((size_t)(b * Sq + s)) * Dq + h * HDq;
        cp[lane] = __float2half_rn(c0[j] * inv);
        cp[lane + 32] = __float2half_rn(c1[j] * inv);
    }
}

// ---------------- host launch ----------------
extern "C" void kernel_launch(void* const* d_in, const int* in_sizes, int n_in,
                              void* d_out, int out_size) {
    const float* x      = (const float*)d_in[0];
    const float* Wu     = (const float*)d_in[1];
    const float* Wk_sel = (const float*)d_in[2];
    const float* Wq_sel = (const float*)d_in[3];
    const float* Wq     = (const float*)d_in[4];
    const float* Wk     = (const float*)d_in[5];
    const float* Wv     = (const float*)d_in[6];
    const float* Wo     = (const float*)d_in[7];
    float* out = (float*)d_out;

    float *xr, *WuT, *WqselT, *WkselT, *part;
    float *pooled, *root, *ksel, *qsel, *q, *k, *v;
    __half *xh, *Wqkv_h, *WoT_h, *ctx_h;
    unsigned char* mask;
    cudaGetSymbolAddress((void**)&xr,      g_xr);
    cudaGetSymbolAddress((void**)&xh,      g_xh);
    cudaGetSymbolAddress((void**)&WuT,     g_WuT);
    cudaGetSymbolAddress((void**)&WqselT,  g_WqselT);
    cudaGetSymbolAddress((void**)&WkselT,  g_WkselT);
    cudaGetSymbolAddress((void**)&Wqkv_h,  g_Wqkv_h);
    cudaGetSymbolAddress((void**)&WoT_h,   g_WoT_h);
    cudaGetSymbolAddress((void**)&part,    g_part);
    cudaGetSymbolAddress((void**)&pooled,  g_pooled);
    cudaGetSymbolAddress((void**)&root,    g_root);
    cudaGetSymbolAddress((void**)&ksel,    g_ksel);
    cudaGetSymbolAddress((void**)&qsel,    g_qsel);
    cudaGetSymbolAddress((void**)&mask,    g_mask);
    cudaGetSymbolAddress((void**)&q,       g_q);
    cudaGetSymbolAddress((void**)&k,       g_k);
    cudaGetSymbolAddress((void**)&v,       g_v);
    cudaGetSymbolAddress((void**)&ctx_h,   g_ctx_h);

    cudaFuncSetAttribute(mma_gemm, cudaFuncAttributeMaxDynamicSharedMemorySize, SM_GEMM_BYTES);
    cudaFuncSetAttribute(mma_gemm_h, cudaFuncAttributeMaxDynamicSharedMemorySize, SM_GEMM_BYTES);

    // (1) x -> xr (tf32) + xh (fp16)
    round_copy_kernel<<<(Mtok * Dq / 4 + 255) / 256, 256>>>(
        (const float4*)x, (float4*)xr, (__half2*)xh, Mtok * Dq / 4);
    // (2) all weight transposes (qkv/Wo -> fp16; rest tf32)
    transpose_all_kernel<<<5632, dim3(32, 8)>>>(Wq_sel, Wq, Wk, Wv, Wu, Wo, Wk_sel,
                                                WqselT, Wqkv_h, WuT, WoT_h, WkselT);
    // (3) pooling
    pool_kernel<<<Bq * Rq, 256>>>(x, pooled);
    // (4-5) root = pooled @ Wu (tf32 split-K + rounded reduce)
    mma_gemm_sk<<<dim3(Dq / 64, (Bq * Rq) / 64, 4), 128>>>(pooled, WuT, part, Bq * Rq, Dq, Dq);
    reduce4_kernel<<<(Bq * Rq * Dq / 4 + 255) / 256, 256>>>((const float4*)part, (float4*)root,
                                                            Bq * Rq * Dq / 4, 1);
    // (6-7) ksel = root @ Wk_sel (tf32 split-K + reduce)
    mma_gemm_sk<<<dim3(DAq / 64, (Bq * Rq) / 64, 4), 128>>>(root, WkselT, part, Bq * Rq, DAq, Dq);
    reduce4_kernel<<<(Bq * Rq * DAq / 4 + 255) / 256, 256>>>((const float4*)part, (float4*)ksel,
                                                             Bq * Rq * DAq / 4, 0);
    // (8) qsel = xr @ Wq_sel^T (tf32 — selection path unchanged from R8)
    mma_gemm<<<dim3(DAq / GBN, Mtok / GBM), 256, SM_GEMM_BYTES>>>(
        xr, WqselT, qsel, Mtok, DAq, Dq);
    // (9) qkv = xh @ Wqkv^T (fp16, routed to [B,H,S,64])
    mma_gemm_h<<<dim3(3 * Dq / GBN, Mtok / GBM), 256, SM_GEMM_BYTES>>>(
        xh, Wqkv_h, nullptr, Mtok, 3 * Dq, Dq, 4, nullptr, q, k, v);
    // (10) selection mask
    select_kernel<<<dim3(Bq, Sq / 8), 256>>>(qsel, ksel, mask);
    // (11) attention (ctx -> fp16)
    attn_kernel<<<dim3(Bq * Hq, Sq / 32), 256>>>(q, k, v, mask, ctx_h);
    // (12) out = ctx_h @ Wo^T + x (fp16 GEMM, fp32 residual)
    mma_gemm_h<<<dim3(Dq / GBN, Mtok / GBM), 256, SM_GEMM_BYTES>>>(
        ctx_h, WoT_h, out, Mtok, Dq, Dq, 2, x, nullptr, nullptr, nullptr);
}

// round 12
// speedup vs baseline: 1.6521x; 1.0618x over previous
#include <cuda_runtime.h>
#include <cuda_fp16.h>
#include <math.h>
#include <stdint.h>

// ---------------- problem constants ----------------
#define Bq 8
#define Sq 1024
#define Dq 1024
#define DAq 256
#define Hq 16
#define HDq 64
#define Rq 32
#define Mtok (Bq*Sq)   // 8192
#define NCAT (DAq + 3*Dq)   // 3328

// ---------------- scratch (device globals; no allocation) ----------------
__device__ __half g_xh[Mtok*Dq];                  // fp16 x
__device__ float g_WuT [Dq*Dq];
__device__ float g_WkselT[DAq*Dq];
__device__ __half g_Wcat_h[NCAT*Dq];              // [qsel|q|k|v] transposed fp16
__device__ __half g_WoT_h[Dq*Dq];
__device__ float g_pooled[Bq*Rq*Dq];
__device__ float g_root  [Bq*Rq*Dq];
__device__ float g_ksel  [Bq*Rq*DAq];
__device__ float g_part[4*256*1024];
__device__ float g_qsel  [Mtok*DAq];
__device__ unsigned char g_mask[Mtok*Rq];
__device__ float g_q [Mtok*Dq];                   // [B,H,S,64]
__device__ float g_k [Mtok*Dq];
__device__ float g_v [Mtok*Dq];
__device__ __half g_ctx_h[Mtok*Dq];               // [B,S,D] fp16

// ---------------- helpers ----------------
__device__ __forceinline__ float rna_tf32(float x) {
    uint32_t r; asm("cvt.rna.tf32.f32 %0, %1;" : "=r"(r) : "f"(x));
    return __uint_as_float(r);
}
__device__ __forceinline__ float warp_max(float v) {
    #pragma unroll
    for (int o = 16; o; o >>= 1) v = fmaxf(v, __shfl_xor_sync(0xffffffffu, v, o));
    return v;
}
__device__ __forceinline__ float warp_sum(float v) {
    #pragma unroll
    for (int o = 16; o; o >>= 1) v += __shfl_xor_sync(0xffffffffu, v, o);
    return v;
}
__device__ __forceinline__ uint32_t smem_u32(const void* p) {
    uint32_t a;
    asm("{ .reg .u64 t; cvta.to.shared.u64 t, %1; cvt.u32.u64 %0, t; }" : "=r"(a) : "l"(p));
    return a;
}

#define CP16(dst, src) \
    asm volatile("cp.async.cg.shared.global [%0], [%1], 16;" :: "r"(dst), "l"(src))
#define CPCOMMIT() asm volatile("cp.async.commit_group;")
#define CPWAIT(n)  asm volatile("cp.async.wait_group %0;" :: "n"(n))

#define LDSM4(r0, r1, r2, r3, addr) \
    asm volatile("ldmatrix.sync.aligned.m8n8.x4.shared.b16 {%0,%1,%2,%3}, [%4];" \
        : "=r"(r0), "=r"(r1), "=r"(r2), "=r"(r3) : "r"(addr))

__device__ __forceinline__ void mma_tf32(float c[4], const uint32_t a[4], const uint32_t b[2]) {
    asm volatile(
        "mma.sync.aligned.m16n8k8.row.col.f32.tf32.tf32.f32 "
        "{%0,%1,%2,%3}, {%4,%5,%6,%7}, {%8,%9}, {%0,%1,%2,%3};"
        : "+f"(c[0]), "+f"(c[1]), "+f"(c[2]), "+f"(c[3])
        : "r"(a[0]), "r"(a[1]), "r"(a[2]), "r"(a[3]), "r"(b[0]), "r"(b[1]));
}
__device__ __forceinline__ void mma_f16(float c[4], const uint32_t a[4], const uint32_t b[2]) {
    asm volatile(
        "mma.sync.aligned.m16n8k16.row.col.f32.f16.f16.f32 "
        "{%0,%1,%2,%3}, {%4,%5,%6,%7}, {%8,%9}, {%0,%1,%2,%3};"
        : "+f"(c[0]), "+f"(c[1]), "+f"(c[2]), "+f"(c[3])
        : "r"(a[0]), "r"(a[1]), "r"(a[2]), "r"(a[3]), "r"(b[0]), "r"(b[1]));
}

// ---------------- prep kernels ----------------
// x -> xh (fp16)
__global__ void round_copy_kernel(const float4* __restrict__ in, __half2* __restrict__ xh, int n4) {
    int i = blockIdx.x * blockDim.x + threadIdx.x;
    if (i < n4) {
        float4 v = in[i];
        xh[2 * i]     = __floats2half2_rn(v.x, v.y);
        xh[2 * i + 1] = __floats2half2_rn(v.z, v.w);
    }
}

// All 7 weight transposes in ONE launch; qsel+qkv+Wo -> fp16, Wu/Wksel -> tf32-fp32.
__global__ void transpose_all_kernel(
    const float* __restrict__ Wq_sel, const float* __restrict__ Wq,
    const float* __restrict__ Wk, const float* __restrict__ Wv,
    const float* __restrict__ Wu, const float* __restrict__ Wo,
    const float* __restrict__ Wk_sel,
    __half* __restrict__ Wcat_h, float* __restrict__ WuT,
    __half* __restrict__ WoT_h, float* __restrict__ WkselT)
{
    __shared__ float t[32][33];
    int tix = blockIdx.x;
    const float* W; int Ndim, seg;
    if (tix < 256)       { seg = 0; W = Wq_sel; Ndim = DAq; }
    else if (tix < 1280) { seg = 1; tix -= 256;  W = Wq; Ndim = Dq; }
    else if (tix < 2304) { seg = 2; tix -= 1280; W = Wk; Ndim = Dq; }
    else if (tix < 3328) { seg = 3; tix -= 2304; W = Wv; Ndim = Dq; }
    else if (tix < 4352) { seg = 4; tix -= 3328; W = Wu; Ndim = Dq; }
    else if (tix < 5376) { seg = 5; tix -= 4352; W = Wo; Ndim = Dq; }
    else                 { seg = 6; tix -= 5376; W = Wk_sel; Ndim = DAq; }
    int ntile = Ndim >> 5;
    int n0 = (tix % ntile) * 32, k0 = (tix / ntile) * 32;
    int tx = threadIdx.x, ty = threadIdx.y;
    #pragma unroll
    for (int i = 0; i < 32; i += 8)
        t[ty + i][tx] = W[(size_t)(k0 + ty + i) * Ndim + n0 + tx];
    __syncthreads();
    if (seg <= 3) {
        size_t base = (seg == 0) ? 0 : (size_t)(DAq + (seg - 1) * Dq) * Dq;
        __half* dst = Wcat_h + base;
        #pragma unroll
        for (int i = 0; i < 32; i += 8)
            dst[(size_t)(n0 + ty + i) * Dq + k0 + tx] = __float2half_rn(t[tx][ty + i]);
    } else if (seg == 5) {
        #pragma unroll
        for (int i = 0; i < 32; i += 8)
            WoT_h[(size_t)(n0 + ty + i) * Dq + k0 + tx] = __float2half_rn(t[tx][ty + i]);
    } else {
        float* dst = (seg == 4) ? WuT : WkselT;
        #pragma unroll
        for (int i = 0; i < 32; i += 8)
            dst[(size_t)(n0 + ty + i) * Dq + k0 + tx] = rna_tf32(t[tx][ty + i]);
    }
}

__global__ void pool_kernel(const float* __restrict__ x, float* __restrict__ pooled) {
    int br = blockIdx.x;
    const float* base = x + (size_t)br * 32 * Dq;
    int d4 = threadIdx.x;
    float4 acc = make_float4(0.f, 0.f, 0.f, 0.f);
    #pragma unroll 4
    for (int i = 0; i < 32; i++) {
        float4 v = *(const float4*)(base + (size_t)i * Dq + d4 * 4);
        acc.x += v.x; acc.y += v.y; acc.z += v.z; acc.w += v.w;
    }
    const float s = 1.0f / 32.0f;
    acc.x = rna_tf32(acc.x * s); acc.y = rna_tf32(acc.y * s);
    acc.z = rna_tf32(acc.z * s); acc.w = rna_tf32(acc.w * s);
    *(float4*)(pooled + (size_t)br * Dq + d4 * 4) = acc;
}

// ---------------- fp16 mma.sync GEMM: 128x128, 256 thr, GBK=64 ----------------
// modes: 2 = +resid (fp32), 4 = fused routing (qsel cols [0,256) + q/k/v -> [B,H,S,64])
#define GBM 128
#define GBN 128
#define GBK 32
#define GBKB 64
#define ROWB 144                      // bytes per row: 64 fp16 (128B) + 16B pad
#define OP_H_BYTES (128 * ROWB)       // 18432
#define STAGE_H_BYTES (2 * OP_H_BYTES)    // 36864
#define SM_GEMM_BYTES (2 * STAGE_H_BYTES) // 73728

__global__ __launch_bounds__(256, 2)
void mma_gemm_h(const __half* __restrict__ A, const __half* __restrict__ Bt,
                float* __restrict__ C, int M, int N, int Kd,
                int mode, const float* __restrict__ resid,
                float* __restrict__ pq, float* __restrict__ pk, float* __restrict__ pv)
{
    extern __shared__ float smf[];
    int tid = threadIdx.x;
    int wid = tid >> 5, lane = tid & 31;
    int warp_row = wid & 1;        // 64 rows each
    int warp_col = wid >> 1;       // 32 cols each
    int gr = lane >> 2, gc = lane & 3;
    int bm = blockIdx.y * GBM;
    int bn = blockIdx.x * GBN;

    int sel = lane >> 3, l8 = lane & 7;
    int a_row_off = (sel & 1) * 8 + l8;
    int a_col16 = (sel >> 1) * 16;     // bytes
    int b_row_off = (sel >> 1) * 8 + l8;
    int b_col16 = (sel & 1) * 16;      // bytes

    float c[4][4][4];
    #pragma unroll
    for (int f = 0; f < 4; f++)
        #pragma unroll
        for (int g = 0; g < 4; g++)
            #pragma unroll
            for (int i = 0; i < 4; i++) c[f][g][i] = 0.f;

    uint32_t sbase = smem_u32(smf);
    const int NK = Kd / GBKB;          // 16

    auto load_stage = [&](int p, int k0) {
        uint32_t Abase = sbase + (uint32_t)(p * STAGE_H_BYTES);
        uint32_t Bbase = Abase + OP_H_BYTES;
        #pragma unroll
        for (int j = 0; j < 4; j++) {
            int idx = tid + j * 256;
            int row = idx >> 3, kc = idx & 7;
            CP16(Abase + (uint32_t)(row * ROWB + kc * 16),
                 A + (size_t)(bm + row) * Kd + k0 + kc * 8);
        }
        #pragma unroll
        for (int j = 0; j < 4; j++) {
            int idx = tid + j * 256;
            int row = idx >> 3, kc = idx & 7;
            CP16(Bbase + (uint32_t)(row * ROWB + kc * 16),
                 Bt + (size_t)(bn + row) * Kd + k0 + kc * 8);
        }
    };

    load_stage(0, 0);
    CPCOMMIT();

    for (int ks = 0; ks < NK; ks++) {
        int p = ks & 1;
        if (ks + 1 < NK) {
            load_stage(p ^ 1, (ks + 1) * GBKB);
            CPCOMMIT();
            CPWAIT(1);
        } else {
            CPWAIT(0);
        }
        __syncthreads();

        uint32_t As = sbase + (uint32_t)(p * STAGE_H_BYTES);
        uint32_t Bs = As + OP_H_BYTES;
        uint32_t aAddr = As + (uint32_t)((warp_row * 64 + a_row_off) * ROWB + a_col16);
        uint32_t bAddr = Bs + (uint32_t)((warp_col * 32 + b_row_off) * ROWB + b_col16);

        #pragma unroll
        for (int kk = 0; kk < 4; kk++) {     // 4 k16 steps per 64-chunk
            uint32_t a[4][4], b[4][2];
            #pragma unroll
            for (int f = 0; f < 4; f++)
                LDSM4(a[f][0], a[f][1], a[f][2], a[f][3],
                      aAddr + (uint32_t)(f * 16 * ROWB + kk * 32));
            #pragma unroll
            for (int gp = 0; gp < 2; gp++)
                LDSM4(b[2*gp][0], b[2*gp][1], b[2*gp+1][0], b[2*gp+1][1],
                      bAddr + (uint32_t)(gp * 16 * ROWB + kk * 32));
            #pragma unroll
            for (int f = 0; f < 4; f++)
                #pragma unroll
                for (int g = 0; g < 4; g++)
                    mma_f16(c[f][g], a[f], b[g]);
        }
        __syncthreads();
    }

    float* stg = smf;
    #pragma unroll
    for (int f = 0; f < 4; f++)
        #pragma unroll
        for (int g = 0; g < 4; g++) {
            int r0 = warp_row * 64 + f * 16 + gr;
            int c0 = warp_col * 32 + g * 8 + 2 * gc;
            stg[r0 * 132 + c0]           = c[f][g][0];
            stg[r0 * 132 + c0 + 1]       = c[f][g][1];
            stg[(r0 + 8) * 132 + c0]     = c[f][g][2];
            stg[(r0 + 8) * 132 + c0 + 1] = c[f][g][3];
        }
    __syncthreads();

    int ccol = (tid & 31) * 4;
    #pragma unroll 4
    for (int rr = 0; rr < 16; rr++) {
        int r = (tid >> 5) + rr * 8;
        float4 v;
        v.x = stg[r * 132 + ccol + 0];
        v.y = stg[r * 132 + ccol + 1];
        v.z = stg[r * 132 + ccol + 2];
        v.w = stg[r * 132 + ccol + 3];
        int m = bm + r;
        int n = bn + ccol;
        if (mode == 2) {
            float4 rv = *(const float4*)(resid + (size_t)m * N + n);
            v.x += rv.x; v.y += rv.y; v.z += rv.z; v.w += rv.w;
            *(float4*)(C + (size_t)m * N + n) = v;
        } else {
            // fused routing: cols [0,256) -> qsel, then q,k,v in [B,H,S,64]
            if (n < DAq) {
                *(float4*)(C + (size_t)m * DAq + n) = v;
            } else {
                int n2 = n - DAq;
                int proj = n2 >> 10, nn = n2 & 1023;
                int h = nn >> 6, hd = nn & 63;
                int b = m >> 10, s = m & 1023;
                float* P = (proj == 0) ? pq : (proj == 1) ? pk : pv;
                *(float4*)(P + (((size_t)(b * Hq + h)) * Sq + s) * HDq + hd) = v;
            }
        }
    }
}

// ---------------- split-K small GEMM (tf32, unchanged) ----------------
#define SKLDT 36
#define SK_STAGE (128 * SKLDT)

__global__ __launch_bounds__(128)
void mma_gemm_sk(const float* __restrict__ A, const float* __restrict__ Bt,
                 float* __restrict__ Cpart, int M, int N, int Kd)
{
    __shared__ float smf[2 * SK_STAGE];
    int tid = threadIdx.x;
    int wid = tid >> 5, lane = tid & 31;
    int warp_row = wid & 1;
    int warp_col = wid >> 1;
    int gr = lane >> 2, gc = lane & 3;
    int bm = blockIdx.y * 64;
    int bn = blockIdx.x * 64;
    int kslice = Kd >> 2;
    int kbase = blockIdx.z * kslice;

    int sel = lane >> 3, l8 = lane & 7;
    int a_row_off = (sel & 1) * 8 + l8;
    int a_col_off = (sel >> 1) * 4;
    int b_row_off = (sel >> 1) * 8 + l8;
    int b_col_off = (sel & 1) * 4;

    float c[2][4][4];
    #pragma unroll
    for (int f = 0; f < 2; f++)
        #pragma unroll
        for (int g = 0; g < 4; g++)
            #pragma unroll
            for (int i = 0; i < 4; i++) c[f][g][i] = 0.f;

    uint32_t sbase = smem_u32(smf);
    const int NK = kslice / GBK;

    auto load_stage = [&](int p, int k0) {
        uint32_t Abase = sbase + (uint32_t)(p * SK_STAGE) * 4;
        uint32_t Bbase = Abase + (uint32_t)(64 * SKLDT) * 4;
        #pragma unroll
        for (int j = 0; j < 4; j++) {
            int idx = tid + j * 128;
            int row = idx >> 3, kc = idx & 7;
            CP16(Abase + (uint32_t)(row * SKLDT + kc * 4) * 4,
                 A + (size_t)(bm + row) * Kd + k0 + kc * 4);
        }
        #pragma unroll
        for (int j = 0; j < 4; j++) {
            int idx = tid + j * 128;
            int row = idx >> 3, kc = idx & 7;
            CP16(Bbase + (uint32_t)(row * SKLDT + kc * 4) * 4,
                 Bt + (size_t)(bn + row) * Kd + k0 + kc * 4);
        }
    };

    load_stage(0, kbase);
    CPCOMMIT();

    for (int ks = 0; ks < NK; ks++) {
        int p = ks & 1;
        if (ks + 1 < NK) {
            load_stage(p ^ 1, kbase + (ks + 1) * GBK);
            CPCOMMIT();
            CPWAIT(1);
        } else {
            CPWAIT(0);
        }
        __syncthreads();

        uint32_t As = sbase + (uint32_t)(p * SK_STAGE) * 4;
        uint32_t Bs = As + (uint32_t)(64 * SKLDT) * 4;
        uint32_t aAddr = As + (uint32_t)((warp_row * 32 + a_row_off) * SKLDT + a_col_off) * 4;
        uint32_t bAddr = Bs + (uint32_t)((warp_col * 32 + b_row_off) * SKLDT + b_col_off) * 4;

        #pragma unroll
        for (int kk = 0; kk < 4; kk++) {
            uint32_t a[2][4], b[4][2];
            #pragma unroll
            for (int f = 0; f < 2; f++)
                LDSM4(a[f][0], a[f][1], a[f][2], a[f][3],
                      aAddr + (uint32_t)(f * 16 * SKLDT + kk * 8) * 4);
            #pragma unroll
            for (int gp = 0; gp < 2; gp++)
                LDSM4(b[2*gp][0], b[2*gp][1], b[2*gp+1][0], b[2*gp+1][1],
                      bAddr + (uint32_t)(gp * 16 * SKLDT + kk * 8) * 4);
            #pragma unroll
            for (int f = 0; f < 2; f++)
                #pragma unroll
                for (int g = 0; g < 4; g++)
                    mma_tf32(c[f][g], a[f], b[g]);
        }
        __syncthreads();
    }

    float* Cp = Cpart + (size_t)blockIdx.z * M * N;
    #pragma unroll
    for (int f = 0; f < 2; f++)
        #pragma unroll
        for (int g = 0; g < 4; g++) {
            int r0 = bm + warp_row * 32 + f * 16 + gr;
            int c0 = bn + warp_col * 32 + g * 8 + 2 * gc;
            *(float2*)(Cp + (size_t)r0 * N + c0)       = make_float2(c[f][g][0], c[f][g][1]);
            *(float2*)(Cp + (size_t)(r0 + 8) * N + c0) = make_float2(c[f][g][2], c[f][g][3]);
        }
}

__global__ void reduce4_kernel(const float4* __restrict__ part, float4* __restrict__ dst,
                               int n4, int do_round) {
    int i = blockIdx.x * blockDim.x + threadIdx.x;
    if (i >= n4) return;
    float4 a = part[i], b = part[i + n4], cc = part[i + 2 * n4], d = part[i + 3 * n4];
    float4 v = make_float4(a.x + b.x + cc.x + d.x, a.y + b.y + cc.y + d.y,
                           a.z + b.z + cc.z + d.z, a.w + b.w + cc.w + d.w);
    if (do_round) {
        v.x = rna_tf32(v.x); v.y = rna_tf32(v.y); v.z = rna_tf32(v.z); v.w = rna_tf32(v.w);
    }
    dst[i] = v;
}

// ---------------- block selection ----------------
__global__ __launch_bounds__(256) void select_kernel(
    const float* __restrict__ qsel, const float* __restrict__ ksel,
    unsigned char* __restrict__ mask)
{
    __shared__ float ks[Rq][DAq + 1];
    __shared__ float qrow[8][DAq];
    int b = blockIdx.x;
    int s0 = blockIdx.y * 8;
    int warp = threadIdx.x >> 5, lane = threadIdx.x & 31;
    int s = s0 + warp;

    const float* kp = ksel + (size_t)b * Rq * DAq;
    for (int i = threadIdx.x; i < Rq * DAq; i += 256)
        ks[i >> 8][i & 255] = kp[i];
    const float* qp = qsel + ((size_t)b * Sq + s) * DAq;
    for (int d = lane; d < DAq; d += 32) qrow[warp][d] = qp[d];
    __syncthreads();

    float logit = 0.f;
    #pragma unroll 8
    for (int d = 0; d < DAq; d++)
        logit += qrow[warp][d] * ks[lane][d];
    logit *= 0.0625f;

    float mx = warp_max(logit);
    float e = expf(logit - mx);
    float sum = warp_sum(e);
    float prob = e / sum;
    bool own = (s >> 5) == lane;
    mask[((size_t)b * Sq + s) * Rq + lane] = (prob >= 0.5f || own) ? 1 : 0;
}

// ---------------- block-sparse attention (32 queries per CTA) ----------------
__global__ __launch_bounds__(256) void attn_kernel(
    const float* __restrict__ Q, const float* __restrict__ K,
    const float* __restrict__ V, const unsigned char* __restrict__ mask,
    __half* __restrict__ ctx)
{
    __shared__ float qs[32][68];
    __shared__ float kt[32][68];
    __shared__ float vt[32][68];
    __shared__ uint32_t qbits[32];
    __shared__ uint32_t needm_s;

    int bh = blockIdx.x;
    int b = bh >> 4, h = bh & 15;
    int qb = blockIdx.y;
    int s0 = qb * 32;
    int tid = threadIdx.x, warp = tid >> 5, lane = tid & 31;

    const float* Qb = Q + ((size_t)bh * Sq + s0) * HDq;
    #pragma unroll
    for (int i = 0; i < 2; i++) {
        int idx = tid + i * 256;
        int row = idx >> 4, col = (idx & 15) << 2;
        float4 f = *(const float4*)(Qb + row * HDq + col);
        qs[row][col] = f.x; qs[row][col+1] = f.y; qs[row][col+2] = f.z; qs[row][col+3] = f.w;
    }

    if (warp == 0) {
        const unsigned char* mrow = mask + ((size_t)b * Sq + s0 + lane) * Rq;
        uint32_t bits = 0;
        #pragma unroll
        for (int r = 0; r < Rq; r++) bits |= (mrow[r] ? 1u : 0u) << r;
        qbits[lane] = bits;
        #pragma unroll
        for (int o = 16; o; o >>= 1) bits |= __shfl_xor_sync(0xffffffffu, bits, o);
        if (lane == 0) needm_s = bits;
    }
    __syncthreads();
    uint32_t need = needm_s;
    uint32_t myb[4];
    #pragma unroll
    for (int j = 0; j < 4; j++) myb[j] = qbits[warp * 4 + j];

    float mr[4], l[4], c0[4], c1[4];
    #pragma unroll
    for (int j = 0; j < 4; j++) { mr[j] = -INFINITY; l[j] = 0.f; c0[j] = 0.f; c1[j] = 0.f; }

    const float* kbh = K + (size_t)bh * Sq * HDq;
    const float* vbh = V + (size_t)bh * Sq * HDq;

    for (int r = 0; r < 32; r++) {
        if (!((need >> r) & 1u)) continue;
        __syncthreads();
        const float* kb = kbh + (size_t)r * 32 * HDq;
        const float* vb = vbh + (size_t)r * 32 * HDq;
        #pragma unroll
        for (int i = 0; i < 2; i++) {
            int idx = tid + i * 256;
            int row = idx >> 4, col = (idx & 15) << 2;
            float4 f = *(const float4*)(kb + row * HDq + col);
            kt[row][col] = f.x; kt[row][col+1] = f.y; kt[row][col+2] = f.z; kt[row][col+3] = f.w;
            float4 g = *(const float4*)(vb + row * HDq + col);
            vt[row][col] = g.x; vt[row][col+1] = g.y; vt[row][col+2] = g.z; vt[row][col+3] = g.w;
        }
        __syncthreads();

        #pragma unroll
        for (int j = 0; j < 4; j++) {
            if (!((myb[j] >> r) & 1u)) continue;
            int qi = warp * 4 + j;
            float sc = 0.f;
            #pragma unroll
            for (int d = 0; d < HDq; d += 4) {
                float4 kv = *(const float4*)&kt[lane][d];
                float4 qv = *(const float4*)&qs[qi][d];
                sc += kv.x * qv.x + kv.y * qv.y + kv.z * qv.z + kv.w * qv.w;
            }
            sc *= 0.125f;
            float bmax = warp_max(sc);
            float mnew = fmaxf(mr[j], bmax);
            float p = __expf(sc - mnew);
            float scale = __expf(mr[j] - mnew);
            l[j] = l[j] * scale + warp_sum(p);
            c0[j] *= scale; c1[j] *= scale;
            #pragma unroll 8
            for (int t = 0; t < 32; t++) {
                float pj = __shfl_sync(0xffffffffu, p, t);
                c0[j] += pj * vt[t][lane];
                c1[j] += pj * vt[t][lane + 32];
            }
            mr[j] = mnew;
        }
    }

    #pragma unroll
    for (int j = 0; j < 4; j++) {
        int s = s0 + warp * 4 + j;
        float inv = 1.0f / l[j];
        __half* cp = ctx + ((size_t)(b * Sq + s)) * Dq + h * HDq;
        cp[lane] = __float2half_rn(c0[j] * inv);
        cp[lane + 32] = __float2half_rn(c1[j] * inv);
    }
}

// ---------------- host launch ----------------
extern "C" void kernel_launch(void* const* d_in, const int* in_sizes, int n_in,
                              void* d_out, int out_size) {
    const float* x      = (const float*)d_in[0];
    const float* Wu     = (const float*)d_in[1];
    const float* Wk_sel = (const float*)d_in[2];
    const float* Wq_sel = (const float*)d_in[3];
    const float* Wq     = (const float*)d_in[4];
    const float* Wk     = (const float*)d_in[5];
    const float* Wv     = (const float*)d_in[6];
    const float* Wo     = (const float*)d_in[7];
    float* out = (float*)d_out;

    float *WuT, *WkselT, *part;
    float *pooled, *root, *ksel, *qsel, *q, *k, *v;
    __half *xh, *Wcat_h, *WoT_h, *ctx_h;
    unsigned char* mask;
    cudaGetSymbolAddress((void**)&xh,      g_xh);
    cudaGetSymbolAddress((void**)&WuT,     g_WuT);
    cudaGetSymbolAddress((void**)&WkselT,  g_WkselT);
    cudaGetSymbolAddress((void**)&Wcat_h,  g_Wcat_h);
    cudaGetSymbolAddress((void**)&WoT_h,   g_WoT_h);
    cudaGetSymbolAddress((void**)&part,    g_part);
    cudaGetSymbolAddress((void**)&pooled,  g_pooled);
    cudaGetSymbolAddress((void**)&root,    g_root);
    cudaGetSymbolAddress((void**)&ksel,    g_ksel);
    cudaGetSymbolAddress((void**)&qsel,    g_qsel);
    cudaGetSymbolAddress((void**)&mask,    g_mask);
    cudaGetSymbolAddress((void**)&q,       g_q);
    cudaGetSymbolAddress((void**)&k,       g_k);
    cudaGetSymbolAddress((void**)&v,       g_v);
    cudaGetSymbolAddress((void**)&ctx_h,   g_ctx_h);

    cudaFuncSetAttribute(mma_gemm_h, cudaFuncAttributeMaxDynamicSharedMemorySize, SM_GEMM_BYTES);

    // (1) x -> xh (fp16)
    round_copy_kernel<<<(Mtok * Dq / 4 + 255) / 256, 256>>>(
        (const float4*)x, (__half2*)xh, Mtok * Dq / 4);
    // (2) all weight transposes (qsel/qkv/Wo -> fp16; Wu/Wksel tf32)
    transpose_all_kernel<<<5632, dim3(32, 8)>>>(Wq_sel, Wq, Wk, Wv, Wu, Wo, Wk_sel,
                                                Wcat_h, WuT, WoT_h, WkselT);
    // (3) pooling
    pool_kernel<<<Bq * Rq, 256>>>(x, pooled);
    // (4) fused fp16: [qsel | q | k | v] = xh @ Wcat^T   <-- profiled launch (#4)
    mma_gemm_h<<<dim3(NCAT / GBN, Mtok / GBM), 256, SM_GEMM_BYTES>>>(
        xh, Wcat_h, qsel, Mtok, NCAT, Dq, 4, nullptr, q, k, v);
    // (5-6) root = pooled @ Wu (tf32 split-K + rounded reduce)
    mma_gemm_sk<<<dim3(Dq / 64, (Bq * Rq) / 64, 4), 128>>>(pooled, WuT, part, Bq * Rq, Dq, Dq);
    reduce4_kernel<<<(Bq * Rq * Dq / 4 + 255) / 256, 256>>>((const float4*)part, (float4*)root,
                                                            Bq * Rq * Dq / 4, 1);
    // (7-8) ksel = root @ Wk_sel (tf32 split-K + reduce)
    mma_gemm_sk<<<dim3(DAq / 64, (Bq * Rq) / 64, 4), 128>>>(root, WkselT, part, Bq * Rq, DAq, Dq);
    reduce4_kernel<<<(Bq * Rq * DAq / 4 + 255) / 256, 256>>>((const float4*)part, (float4*)ksel,
                                                             Bq * Rq * DAq / 4, 0);
    // (9) selection mask
    select_kernel<<<dim3(Bq, Sq / 8), 256>>>(qsel, ksel, mask);
    // (10) attention (ctx -> fp16)
    attn_kernel<<<dim3(Bq * Hq, Sq / 32), 256>>>(q, k, v, mask, ctx_h);
    // (11) out = ctx_h @ Wo^T + x (fp16 GEMM, fp32 residual)
    mma_gemm_h<<<dim3(Dq / GBN, Mtok / GBM), 256, SM_GEMM_BYTES>>>(
        ctx_h, WoT_h, out, Mtok, Dq, Dq, 2, x, nullptr, nullptr, nullptr);
}

// round 13
// speedup vs baseline: 1.6522x; 1.0001x over previous
#include <cuda_runtime.h>
#include <cuda_fp16.h>
#include <math.h>
#include <stdint.h>

// ---------------- problem constants ----------------
#define Bq 8
#define Sq 1024
#define Dq 1024
#define DAq 256
#define Hq 16
#define HDq 64
#define Rq 32
#define Mtok (Bq*Sq)   // 8192
#define NCAT (DAq + 3*Dq)   // 3328

// ---------------- scratch (device globals; no allocation) ----------------
__device__ __half g_xh[Mtok*Dq];                  // fp16 x
__device__ float g_WuT [Dq*Dq];
__device__ float g_WkselT[DAq*Dq];
__device__ __half g_Wcat_h[NCAT*Dq];              // [qsel|q|k|v] transposed fp16
__device__ __half g_WoT_h[Dq*Dq];
__device__ float g_pooled[Bq*Rq*Dq];
__device__ float g_root  [Bq*Rq*Dq];
__device__ float g_ksel  [Bq*Rq*DAq];
__device__ float g_part[4*256*1024];
__device__ float g_qsel  [Mtok*DAq];
__device__ unsigned char g_mask[Mtok*Rq];
__device__ __half g_q [Mtok*Dq];                  // [B,H,S,64] fp16
__device__ __half g_k [Mtok*Dq];
__device__ __half g_v [Mtok*Dq];
__device__ __half g_ctx_h[Mtok*Dq];               // [B,S,D] fp16

// ---------------- helpers ----------------
__device__ __forceinline__ float rna_tf32(float x) {
    uint32_t r; asm("cvt.rna.tf32.f32 %0, %1;" : "=r"(r) : "f"(x));
    return __uint_as_float(r);
}
__device__ __forceinline__ float warp_max(float v) {
    #pragma unroll
    for (int o = 16; o; o >>= 1) v = fmaxf(v, __shfl_xor_sync(0xffffffffu, v, o));
    return v;
}
__device__ __forceinline__ float warp_sum(float v) {
    #pragma unroll
    for (int o = 16; o; o >>= 1) v += __shfl_xor_sync(0xffffffffu, v, o);
    return v;
}
__device__ __forceinline__ uint32_t smem_u32(const void* p) {
    uint32_t a;
    asm("{ .reg .u64 t; cvta.to.shared.u64 t, %1; cvt.u32.u64 %0, t; }" : "=r"(a) : "l"(p));
    return a;
}

#define CP16(dst, src) \
    asm volatile("cp.async.cg.shared.global [%0], [%1], 16;" :: "r"(dst), "l"(src))
#define CPCOMMIT() asm volatile("cp.async.commit_group;")
#define CPWAIT(n)  asm volatile("cp.async.wait_group %0;" :: "n"(n))

#define LDSM4(r0, r1, r2, r3, addr) \
    asm volatile("ldmatrix.sync.aligned.m8n8.x4.shared.b16 {%0,%1,%2,%3}, [%4];" \
        : "=r"(r0), "=r"(r1), "=r"(r2), "=r"(r3) : "r"(addr))

__device__ __forceinline__ void mma_tf32(float c[4], const uint32_t a[4], const uint32_t b[2]) {
    asm volatile(
        "mma.sync.aligned.m16n8k8.row.col.f32.tf32.tf32.f32 "
        "{%0,%1,%2,%3}, {%4,%5,%6,%7}, {%8,%9}, {%0,%1,%2,%3};"
        : "+f"(c[0]), "+f"(c[1]), "+f"(c[2]), "+f"(c[3])
        : "r"(a[0]), "r"(a[1]), "r"(a[2]), "r"(a[3]), "r"(b[0]), "r"(b[1]));
}
__device__ __forceinline__ void mma_f16(float c[4], const uint32_t a[4], const uint32_t b[2]) {
    asm volatile(
        "mma.sync.aligned.m16n8k16.row.col.f32.f16.f16.f32 "
        "{%0,%1,%2,%3}, {%4,%5,%6,%7}, {%8,%9}, {%0,%1,%2,%3};"
        : "+f"(c[0]), "+f"(c[1]), "+f"(c[2]), "+f"(c[3])
        : "r"(a[0]), "r"(a[1]), "r"(a[2]), "r"(a[3]), "r"(b[0]), "r"(b[1]));
}

// ---------------- prep kernels ----------------
__global__ void round_copy_kernel(const float4* __restrict__ in, __half2* __restrict__ xh, int n4) {
    int i = blockIdx.x * blockDim.x + threadIdx.x;
    if (i < n4) {
        float4 v = in[i];
        xh[2 * i]     = __floats2half2_rn(v.x, v.y);
        xh[2 * i + 1] = __floats2half2_rn(v.z, v.w);
    }
}

// All 7 weight transposes in ONE launch; qsel+qkv+Wo -> fp16, Wu/Wksel -> tf32-fp32.
__global__ void transpose_all_kernel(
    const float* __restrict__ Wq_sel, const float* __restrict__ Wq,
    const float* __restrict__ Wk, const float* __restrict__ Wv,
    const float* __restrict__ Wu, const float* __restrict__ Wo,
    const float* __restrict__ Wk_sel,
    __half* __restrict__ Wcat_h, float* __restrict__ WuT,
    __half* __restrict__ WoT_h, float* __restrict__ WkselT)
{
    __shared__ float t[32][33];
    int tix = blockIdx.x;
    const float* W; int Ndim, seg;
    if (tix < 256)       { seg = 0; W = Wq_sel; Ndim = DAq; }
    else if (tix < 1280) { seg = 1; tix -= 256;  W = Wq; Ndim = Dq; }
    else if (tix < 2304) { seg = 2; tix -= 1280; W = Wk; Ndim = Dq; }
    else if (tix < 3328) { seg = 3; tix -= 2304; W = Wv; Ndim = Dq; }
    else if (tix < 4352) { seg = 4; tix -= 3328; W = Wu; Ndim = Dq; }
    else if (tix < 5376) { seg = 5; tix -= 4352; W = Wo; Ndim = Dq; }
    else                 { seg = 6; tix -= 5376; W = Wk_sel; Ndim = DAq; }
    int ntile = Ndim >> 5;
    int n0 = (tix % ntile) * 32, k0 = (tix / ntile) * 32;
    int tx = threadIdx.x, ty = threadIdx.y;
    #pragma unroll
    for (int i = 0; i < 32; i += 8)
        t[ty + i][tx] = W[(size_t)(k0 + ty + i) * Ndim + n0 + tx];
    __syncthreads();
    if (seg <= 3) {
        size_t base = (seg == 0) ? 0 : (size_t)(DAq + (seg - 1) * Dq) * Dq;
        __half* dst = Wcat_h + base;
        #pragma unroll
        for (int i = 0; i < 32; i += 8)
            dst[(size_t)(n0 + ty + i) * Dq + k0 + tx] = __float2half_rn(t[tx][ty + i]);
    } else if (seg == 5) {
        #pragma unroll
        for (int i = 0; i < 32; i += 8)
            WoT_h[(size_t)(n0 + ty + i) * Dq + k0 + tx] = __float2half_rn(t[tx][ty + i]);
    } else {
        float* dst = (seg == 4) ? WuT : WkselT;
        #pragma unroll
        for (int i = 0; i < 32; i += 8)
            dst[(size_t)(n0 + ty + i) * Dq + k0 + tx] = rna_tf32(t[tx][ty + i]);
    }
}

__global__ void pool_kernel(const float* __restrict__ x, float* __restrict__ pooled) {
    int br = blockIdx.x;
    const float* base = x + (size_t)br * 32 * Dq;
    int d4 = threadIdx.x;
    float4 acc = make_float4(0.f, 0.f, 0.f, 0.f);
    #pragma unroll 4
    for (int i = 0; i < 32; i++) {
        float4 v = *(const float4*)(base + (size_t)i * Dq + d4 * 4);
        acc.x += v.x; acc.y += v.y; acc.z += v.z; acc.w += v.w;
    }
    const float s = 1.0f / 32.0f;
    acc.x = rna_tf32(acc.x * s); acc.y = rna_tf32(acc.y * s);
    acc.z = rna_tf32(acc.z * s); acc.w = rna_tf32(acc.w * s);
    *(float4*)(pooled + (size_t)br * Dq + d4 * 4) = acc;
}

// ---------------- fp16 mma.sync GEMM: 128x128, 256 thr, GBK=64 ----------------
// modes: 2 = +resid (fp32 out), 4 = fused routing (qsel fp32 + q/k/v fp16 [B,H,S,64])
#define GBM 128
#define GBN 128
#define GBK 32
#define GBKB 64
#define ROWB 144
#define OP_H_BYTES (128 * ROWB)
#define STAGE_H_BYTES (2 * OP_H_BYTES)
#define SM_GEMM_BYTES (2 * STAGE_H_BYTES) // 73728

__global__ __launch_bounds__(256, 2)
void mma_gemm_h(const __half* __restrict__ A, const __half* __restrict__ Bt,
                float* __restrict__ C, int M, int N, int Kd,
                int mode, const float* __restrict__ resid,
                __half* __restrict__ pq, __half* __restrict__ pk, __half* __restrict__ pv)
{
    extern __shared__ float smf[];
    int tid = threadIdx.x;
    int wid = tid >> 5, lane = tid & 31;
    int warp_row = wid & 1;
    int warp_col = wid >> 1;
    int gr = lane >> 2, gc = lane & 3;
    int bm = blockIdx.y * GBM;
    int bn = blockIdx.x * GBN;

    int sel = lane >> 3, l8 = lane & 7;
    int a_row_off = (sel & 1) * 8 + l8;
    int a_col16 = (sel >> 1) * 16;
    int b_row_off = (sel >> 1) * 8 + l8;
    int b_col16 = (sel & 1) * 16;

    float c[4][4][4];
    #pragma unroll
    for (int f = 0; f < 4; f++)
        #pragma unroll
        for (int g = 0; g < 4; g++)
            #pragma unroll
            for (int i = 0; i < 4; i++) c[f][g][i] = 0.f;

    uint32_t sbase = smem_u32(smf);
    const int NK = Kd / GBKB;

    auto load_stage = [&](int p, int k0) {
        uint32_t Abase = sbase + (uint32_t)(p * STAGE_H_BYTES);
        uint32_t Bbase = Abase + OP_H_BYTES;
        #pragma unroll
        for (int j = 0; j < 4; j++) {
            int idx = tid + j * 256;
            int row = idx >> 3, kc = idx & 7;
            CP16(Abase + (uint32_t)(row * ROWB + kc * 16),
                 A + (size_t)(bm + row) * Kd + k0 + kc * 8);
        }
        #pragma unroll
        for (int j = 0; j < 4; j++) {
            int idx = tid + j * 256;
            int row = idx >> 3, kc = idx & 7;
            CP16(Bbase + (uint32_t)(row * ROWB + kc * 16),
                 Bt + (size_t)(bn + row) * Kd + k0 + kc * 8);
        }
    };

    load_stage(0, 0);
    CPCOMMIT();

    for (int ks = 0; ks < NK; ks++) {
        int p = ks & 1;
        if (ks + 1 < NK) {
            load_stage(p ^ 1, (ks + 1) * GBKB);
            CPCOMMIT();
            CPWAIT(1);
        } else {
            CPWAIT(0);
        }
        __syncthreads();

        uint32_t As = sbase + (uint32_t)(p * STAGE_H_BYTES);
        uint32_t Bs = As + OP_H_BYTES;
        uint32_t aAddr = As + (uint32_t)((warp_row * 64 + a_row_off) * ROWB + a_col16);
        uint32_t bAddr = Bs + (uint32_t)((warp_col * 32 + b_row_off) * ROWB + b_col16);

        #pragma unroll
        for (int kk = 0; kk < 4; kk++) {
            uint32_t a[4][4], b[4][2];
            #pragma unroll
            for (int f = 0; f < 4; f++)
                LDSM4(a[f][0], a[f][1], a[f][2], a[f][3],
                      aAddr + (uint32_t)(f * 16 * ROWB + kk * 32));
            #pragma unroll
            for (int gp = 0; gp < 2; gp++)
                LDSM4(b[2*gp][0], b[2*gp][1], b[2*gp+1][0], b[2*gp+1][1],
                      bAddr + (uint32_t)(gp * 16 * ROWB + kk * 32));
            #pragma unroll
            for (int f = 0; f < 4; f++)
                #pragma unroll
                for (int g = 0; g < 4; g++)
                    mma_f16(c[f][g], a[f], b[g]);
        }
        __syncthreads();
    }

    float* stg = smf;
    #pragma unroll
    for (int f = 0; f < 4; f++)
        #pragma unroll
        for (int g = 0; g < 4; g++) {
            int r0 = warp_row * 64 + f * 16 + gr;
            int c0 = warp_col * 32 + g * 8 + 2 * gc;
            stg[r0 * 132 + c0]           = c[f][g][0];
            stg[r0 * 132 + c0 + 1]       = c[f][g][1];
            stg[(r0 + 8) * 132 + c0]     = c[f][g][2];
            stg[(r0 + 8) * 132 + c0 + 1] = c[f][g][3];
        }
    __syncthreads();

    int ccol = (tid & 31) * 4;
    #pragma unroll 4
    for (int rr = 0; rr < 16; rr++) {
        int r = (tid >> 5) + rr * 8;
        float4 v;
        v.x = stg[r * 132 + ccol + 0];
        v.y = stg[r * 132 + ccol + 1];
        v.z = stg[r * 132 + ccol + 2];
        v.w = stg[r * 132 + ccol + 3];
        int m = bm + r;
        int n = bn + ccol;
        if (mode == 2) {
            float4 rv = *(const float4*)(resid + (size_t)m * N + n);
            v.x += rv.x; v.y += rv.y; v.z += rv.z; v.w += rv.w;
            *(float4*)(C + (size_t)m * N + n) = v;
        } else {
            if (n < DAq) {
                *(float4*)(C + (size_t)m * DAq + n) = v;
            } else {
                int n2 = n - DAq;
                int proj = n2 >> 10, nn = n2 & 1023;
                int h = nn >> 6, hd = nn & 63;
                int b = m >> 10, s = m & 1023;
                __half* P = (proj == 0) ? pq : (proj == 1) ? pk : pv;
                __half2 h01 = __floats2half2_rn(v.x, v.y);
                __half2 h23 = __floats2half2_rn(v.z, v.w);
                uint2 u = make_uint2(*(uint32_t*)&h01, *(uint32_t*)&h23);
                *(uint2*)(P + (((size_t)(b * Hq + h)) * Sq + s) * HDq + hd) = u;
            }
        }
    }
}

// ---------------- split-K small GEMM (tf32, unchanged) ----------------
#define SKLDT 36
#define SK_STAGE (128 * SKLDT)

__global__ __launch_bounds__(128)
void mma_gemm_sk(const float* __restrict__ A, const float* __restrict__ Bt,
                 float* __restrict__ Cpart, int M, int N, int Kd)
{
    __shared__ float smf[2 * SK_STAGE];
    int tid = threadIdx.x;
    int wid = tid >> 5, lane = tid & 31;
    int warp_row = wid & 1;
    int warp_col = wid >> 1;
    int gr = lane >> 2, gc = lane & 3;
    int bm = blockIdx.y * 64;
    int bn = blockIdx.x * 64;
    int kslice = Kd >> 2;
    int kbase = blockIdx.z * kslice;

    int sel = lane >> 3, l8 = lane & 7;
    int a_row_off = (sel & 1) * 8 + l8;
    int a_col_off = (sel >> 1) * 4;
    int b_row_off = (sel >> 1) * 8 + l8;
    int b_col_off = (sel & 1) * 4;

    float c[2][4][4];
    #pragma unroll
    for (int f = 0; f < 2; f++)
        #pragma unroll
        for (int g = 0; g < 4; g++)
            #pragma unroll
            for (int i = 0; i < 4; i++) c[f][g][i] = 0.f;

    uint32_t sbase = smem_u32(smf);
    const int NK = kslice / GBK;

    auto load_stage = [&](int p, int k0) {
        uint32_t Abase = sbase + (uint32_t)(p * SK_STAGE) * 4;
        uint32_t Bbase = Abase + (uint32_t)(64 * SKLDT) * 4;
        #pragma unroll
        for (int j = 0; j < 4; j++) {
            int idx = tid + j * 128;
            int row = idx >> 3, kc = idx & 7;
            CP16(Abase + (uint32_t)(row * SKLDT + kc * 4) * 4,
                 A + (size_t)(bm + row) * Kd + k0 + kc * 4);
        }
        #pragma unroll
        for (int j = 0; j < 4; j++) {
            int idx = tid + j * 128;
            int row = idx >> 3, kc = idx & 7;
            CP16(Bbase + (uint32_t)(row * SKLDT + kc * 4) * 4,
                 Bt + (size_t)(bn + row) * Kd + k0 + kc * 4);
        }
    };

    load_stage(0, kbase);
    CPCOMMIT();

    for (int ks = 0; ks < NK; ks++) {
        int p = ks & 1;
        if (ks + 1 < NK) {
            load_stage(p ^ 1, kbase + (ks + 1) * GBK);
            CPCOMMIT();
            CPWAIT(1);
        } else {
            CPWAIT(0);
        }
        __syncthreads();

        uint32_t As = sbase + (uint32_t)(p * SK_STAGE) * 4;
        uint32_t Bs = As + (uint32_t)(64 * SKLDT) * 4;
        uint32_t aAddr = As + (uint32_t)((warp_row * 32 + a_row_off) * SKLDT + a_col_off) * 4;
        uint32_t bAddr = Bs + (uint32_t)((warp_col * 32 + b_row_off) * SKLDT + b_col_off) * 4;

        #pragma unroll
        for (int kk = 0; kk < 4; kk++) {
            uint32_t a[2][4], b[4][2];
            #pragma unroll
            for (int f = 0; f < 2; f++)
                LDSM4(a[f][0], a[f][1], a[f][2], a[f][3],
                      aAddr + (uint32_t)(f * 16 * SKLDT + kk * 8) * 4);
            #pragma unroll
            for (int gp = 0; gp < 2; gp++)
                LDSM4(b[2*gp][0], b[2*gp][1], b[2*gp+1][0], b[2*gp+1][1],
                      bAddr + (uint32_t)(gp * 16 * SKLDT + kk * 8) * 4);
            #pragma unroll
            for (int f = 0; f < 2; f++)
                #pragma unroll
                for (int g = 0; g < 4; g++)
                    mma_tf32(c[f][g], a[f], b[g]);
        }
        __syncthreads();
    }

    float* Cp = Cpart + (size_t)blockIdx.z * M * N;
    #pragma unroll
    for (int f = 0; f < 2; f++)
        #pragma unroll
        for (int g = 0; g < 4; g++) {
            int r0 = bm + warp_row * 32 + f * 16 + gr;
            int c0 = bn + warp_col * 32 + g * 8 + 2 * gc;
            *(float2*)(Cp + (size_t)r0 * N + c0)       = make_float2(c[f][g][0], c[f][g][1]);
            *(float2*)(Cp + (size_t)(r0 + 8) * N + c0) = make_float2(c[f][g][2], c[f][g][3]);
        }
}

__global__ void reduce4_kernel(const float4* __restrict__ part, float4* __restrict__ dst,
                               int n4, int do_round) {
    int i = blockIdx.x * blockDim.x + threadIdx.x;
    if (i >= n4) return;
    float4 a = part[i], b = part[i + n4], cc = part[i + 2 * n4], d = part[i + 3 * n4];
    float4 v = make_float4(a.x + b.x + cc.x + d.x, a.y + b.y + cc.y + d.y,
                           a.z + b.z + cc.z + d.z, a.w + b.w + cc.w + d.w);
    if (do_round) {
        v.x = rna_tf32(v.x); v.y = rna_tf32(v.y); v.z = rna_tf32(v.z); v.w = rna_tf32(v.w);
    }
    dst[i] = v;
}

// ---------------- block selection ----------------
__global__ __launch_bounds__(256) void select_kernel(
    const float* __restrict__ qsel, const float* __restrict__ ksel,
    unsigned char* __restrict__ mask)
{
    __shared__ float ks[Rq][DAq + 1];
    __shared__ float qrow[8][DAq];
    int b = blockIdx.x;
    int s0 = blockIdx.y * 8;
    int warp = threadIdx.x >> 5, lane = threadIdx.x & 31;
    int s = s0 + warp;

    const float* kp = ksel + (size_t)b * Rq * DAq;
    for (int i = threadIdx.x; i < Rq * DAq; i += 256)
        ks[i >> 8][i & 255] = kp[i];
    const float* qp = qsel + ((size_t)b * Sq + s) * DAq;
    for (int d = lane; d < DAq; d += 32) qrow[warp][d] = qp[d];
    __syncthreads();

    float logit = 0.f;
    #pragma unroll 8
    for (int d = 0; d < DAq; d++)
        logit += qrow[warp][d] * ks[lane][d];
    logit *= 0.0625f;

    float mx = warp_max(logit);
    float e = expf(logit - mx);
    float sum = warp_sum(e);
    float prob = e / sum;
    bool own = (s >> 5) == lane;
    mask[((size_t)b * Sq + s) * Rq + lane] = (prob >= 0.5f || own) ? 1 : 0;
}

// ---------------- block-sparse attention (32 queries per CTA, fp16 q/k/v) ----------------
__global__ __launch_bounds__(256) void attn_kernel(
    const __half* __restrict__ Q, const __half* __restrict__ K,
    const __half* __restrict__ V, const unsigned char* __restrict__ mask,
    __half* __restrict__ ctx)
{
    __shared__ float qs[32][68];
    __shared__ float kt[32][68];
    __shared__ float vt[32][68];
    __shared__ uint32_t qbits[32];
    __shared__ uint32_t needm_s;

    int bh = blockIdx.x;
    int b = bh >> 4, h = bh & 15;
    int qb = blockIdx.y;
    int s0 = qb * 32;
    int tid = threadIdx.x, warp = tid >> 5, lane = tid & 31;

    // Q tile: 32x64 halves = 4096 B = 256 threads x uint4
    {
        int row = tid >> 3, c8 = (tid & 7) * 8;
        uint4 raw = *(const uint4*)(Q + ((size_t)bh * Sq + s0 + row) * HDq + c8);
        const __half2* hp = (const __half2*)&raw;
        #pragma unroll
        for (int j = 0; j < 4; j++) {
            float2 f = __half22float2(hp[j]);
            qs[row][c8 + 2 * j] = f.x;
            qs[row][c8 + 2 * j + 1] = f.y;
        }
    }

    if (warp == 0) {
        const unsigned char* mrow = mask + ((size_t)b * Sq + s0 + lane) * Rq;
        uint32_t bits = 0;
        #pragma unroll
        for (int r = 0; r < Rq; r++) bits |= (mrow[r] ? 1u : 0u) << r;
        qbits[lane] = bits;
        #pragma unroll
        for (int o = 16; o; o >>= 1) bits |= __shfl_xor_sync(0xffffffffu, bits, o);
        if (lane == 0) needm_s = bits;
    }
    __syncthreads();
    uint32_t need = needm_s;
    uint32_t myb[4];
    #pragma unroll
    for (int j = 0; j < 4; j++) myb[j] = qbits[warp * 4 + j];

    float mr[4], l[4], c0[4], c1[4];
    #pragma unroll
    for (int j = 0; j < 4; j++) { mr[j] = -INFINITY; l[j] = 0.f; c0[j] = 0.f; c1[j] = 0.f; }

    const __half* kbh = K + (size_t)bh * Sq * HDq;
    const __half* vbh = V + (size_t)bh * Sq * HDq;

    for (int r = 0; r < 32; r++) {
        if (!((need >> r) & 1u)) continue;
        __syncthreads();
        const __half* kb = kbh + (size_t)r * 32 * HDq;
        const __half* vb = vbh + (size_t)r * 32 * HDq;
        {
            int row = tid >> 3, c8 = (tid & 7) * 8;
            uint4 rk = *(const uint4*)(kb + row * HDq + c8);
            uint4 rv = *(const uint4*)(vb + row * HDq + c8);
            const __half2* hk = (const __half2*)&rk;
            const __half2* hv = (const __half2*)&rv;
            #pragma unroll
            for (int j = 0; j < 4; j++) {
                float2 fk = __half22float2(hk[j]);
                float2 fv = __half22float2(hv[j]);
                kt[row][c8 + 2 * j] = fk.x; kt[row][c8 + 2 * j + 1] = fk.y;
                vt[row][c8 + 2 * j] = fv.x; vt[row][c8 + 2 * j + 1] = fv.y;
            }
        }
        __syncthreads();

        #pragma unroll
        for (int j = 0; j < 4; j++) {
            if (!((myb[j] >> r) & 1u)) continue;
            int qi = warp * 4 + j;
            float sc = 0.f;
            #pragma unroll
            for (int d = 0; d < HDq; d += 4) {
                float4 kv = *(const float4*)&kt[lane][d];
                float4 qv = *(const float4*)&qs[qi][d];
                sc += kv.x * qv.x + kv.y * qv.y + kv.z * qv.z + kv.w * qv.w;
            }
            sc *= 0.125f;
            float bmax = warp_max(sc);
            float mnew = fmaxf(mr[j], bmax);
            float p = __expf(sc - mnew);
            float scale = __expf(mr[j] - mnew);
            l[j] = l[j] * scale + warp_sum(p);
            c0[j] *= scale; c1[j] *= scale;
            #pragma unroll 8
            for (int t = 0; t < 32; t++) {
                float pj = __shfl_sync(0xffffffffu, p, t);
                c0[j] += pj * vt[t][lane];
                c1[j] += pj * vt[t][lane + 32];
            }
            mr[j] = mnew;
        }
    }

    #pragma unroll
    for (int j = 0; j < 4; j++) {
        int s = s0 + warp * 4 + j;
        float inv = 1.0f / l[j];
        __half* cp = ctx + ((size_t)(b * Sq + s)) * Dq + h * HDq;
        cp[lane] = __float2half_rn(c0[j] * inv);
        cp[lane + 32] = __float2half_rn(c1[j] * inv);
    }
}

// ---------------- host launch ----------------
extern "C" void kernel_launch(void* const* d_in, const int* in_sizes, int n_in,
                              void* d_out, int out_size) {
    const float* x      = (const float*)d_in[0];
    const float* Wu     = (const float*)d_in[1];
    const float* Wk_sel = (const float*)d_in[2];
    const float* Wq_sel = (const float*)d_in[3];
    const float* Wq     = (const float*)d_in[4];
    const float* Wk     = (const float*)d_in[5];
    const float* Wv     = (const float*)d_in[6];
    const float* Wo     = (const float*)d_in[7];
    float* out = (float*)d_out;

    float *WuT, *WkselT, *part;
    float *pooled, *root, *ksel, *qsel;
    __half *xh, *Wcat_h, *WoT_h, *ctx_h, *q, *k, *v;
    unsigned char* mask;
    cudaGetSymbolAddress((void**)&xh,      g_xh);
    cudaGetSymbolAddress((void**)&WuT,     g_WuT);
    cudaGetSymbolAddress((void**)&WkselT,  g_WkselT);
    cudaGetSymbolAddress((void**)&Wcat_h,  g_Wcat_h);
    cudaGetSymbolAddress((void**)&WoT_h,   g_WoT_h);
    cudaGetSymbolAddress((void**)&part,    g_part);
    cudaGetSymbolAddress((void**)&pooled,  g_pooled);
    cudaGetSymbolAddress((void**)&root,    g_root);
    cudaGetSymbolAddress((void**)&ksel,    g_ksel);
    cudaGetSymbolAddress((void**)&qsel,    g_qsel);
    cudaGetSymbolAddress((void**)&mask,    g_mask);
    cudaGetSymbolAddress((void**)&q,       g_q);
    cudaGetSymbolAddress((void**)&k,       g_k);
    cudaGetSymbolAddress((void**)&v,       g_v);
    cudaGetSymbolAddress((void**)&ctx_h,   g_ctx_h);

    cudaFuncSetAttribute(mma_gemm_h, cudaFuncAttributeMaxDynamicSharedMemorySize, SM_GEMM_BYTES);

    // (1) x -> xh (fp16)
    round_copy_kernel<<<(Mtok * Dq / 4 + 255) / 256, 256>>>(
        (const float4*)x, (__half2*)xh, Mtok * Dq / 4);
    // (2) all weight transposes
    transpose_all_kernel<<<5632, dim3(32, 8)>>>(Wq_sel, Wq, Wk, Wv, Wu, Wo, Wk_sel,
                                                Wcat_h, WuT, WoT_h, WkselT);
    // (3) pooling
    pool_kernel<<<Bq * Rq, 256>>>(x, pooled);
    // (4) fused fp16: [qsel | q | k | v] = xh @ Wcat^T (q/k/v stored fp16)
    mma_gemm_h<<<dim3(NCAT / GBN, Mtok / GBM), 256, SM_GEMM_BYTES>>>(
        xh, Wcat_h, qsel, Mtok, NCAT, Dq, 4, nullptr, q, k, v);
    // (5-6) root = pooled @ Wu (tf32 split-K + rounded reduce)
    mma_gemm_sk<<<dim3(Dq / 64, (Bq * Rq) / 64, 4), 128>>>(pooled, WuT, part, Bq * Rq, Dq, Dq);
    reduce4_kernel<<<(Bq * Rq * Dq / 4 + 255) / 256, 256>>>((const float4*)part, (float4*)root,
                                                            Bq * Rq * Dq / 4, 1);
    // (7-8) ksel = root @ Wk_sel (tf32 split-K + reduce)
    mma_gemm_sk<<<dim3(DAq / 64, (Bq * Rq) / 64, 4), 128>>>(root, WkselT, part, Bq * Rq, DAq, Dq);
    reduce4_kernel<<<(Bq * Rq * DAq / 4 + 255) / 256, 256>>>((const float4*)part, (float4*)ksel,
                                                             Bq * Rq * DAq / 4, 0);
    // (9) selection mask
    select_kernel<<<dim3(Bq, Sq / 8), 256>>>(qsel, ksel, mask);
    // (10) attention (fp16 q/k/v in, ctx fp16 out)
    attn_kernel<<<dim3(Bq * Hq, Sq / 32), 256>>>(q, k, v, mask, ctx_h);
    // (11) out = ctx_h @ Wo^T + x (fp16 GEMM, fp32 residual)
    mma_gemm_h<<<dim3(Dq / GBN, Mtok / GBM), 256, SM_GEMM_BYTES>>>(
        ctx_h, WoT_h, out, Mtok, Dq, Dq, 2, x, nullptr, nullptr, nullptr);
}